// round 9
// baseline (speedup 1.0000x reference)
#include <cuda_runtime.h>
#include <cuda_fp16.h>
#include <cstdint>

#define N_NODES 100000
#define N_EDGES 2000000
#define DIM     64
#define F_IN    128
#define R_REL   64
#define ER_REL  2048
#define RF_REL  64
#define NCLS    16

// ---------------- scratch (static device memory; no allocations) ----------------
__device__ __align__(16) float g_x0[N_NODES * DIM];        // x2 (fp32, for out_kernel)
__device__ __align__(16) float g_agg[N_NODES * DIM];       // scatter accumulator
__device__ __align__(16) __half2 g_x0h[N_NODES * DIM / 2]; // fp16 mirror of x0 (proj out)
__device__ __align__(16) __half2 g_x1h[N_NODES * DIM / 2]; // fp16 mirror of x1 (conv1 out)
__device__ int g_cnt[N_NODES];                             // degree (by dst)
__device__ int g_cur[N_NODES];                             // fill cursors
__device__ __align__(16) float g_wrel[R_REL * DIM];        // per-relation edge weights
__device__ __align__(16) unsigned long long g_eadj64[N_EDGES]; // (src<<23)|(et<<17)|dst, dst-sorted

// ---------------- helpers ----------------
__device__ __forceinline__ void red_add_v4(float* addr, float4 v) {
    asm volatile("red.global.add.v4.f32 [%0], {%1, %2, %3, %4};"
                 :: "l"(addr), "f"(v.x), "f"(v.y), "f"(v.z), "f"(v.w)
                 : "memory");
}
__device__ __forceinline__ void red_add_s32(int* addr, int v) {
    asm volatile("red.global.add.s32 [%0], %1;" :: "l"(addr), "r"(v) : "memory");
}

// ---------------- build: dst-sorted edge list ----------------
__global__ void zero_kernel() {
    int i = blockIdx.x * blockDim.x + threadIdx.x;
    if (i < N_NODES * DIM / 4) ((float4*)g_agg)[i] = make_float4(0.f, 0.f, 0.f, 0.f);
    if (i < N_NODES) g_cnt[i] = 0;
}

__global__ void count_kernel(const int* __restrict__ dst) {
    int e = blockIdx.x * blockDim.x + threadIdx.x;
    if (e < N_EDGES) red_add_s32(&g_cnt[dst[e]], 1);
}

__global__ void scan_kernel() {
    __shared__ int ps[1024];
    int tid = threadIdx.x;
    const int CH = 98;  // 1024*98 >= 100000
    int lo = tid * CH;
    int hi = min(lo + CH, N_NODES);
    int sum = 0;
    for (int i = lo; i < hi; ++i) sum += g_cnt[i];
    ps[tid] = sum;
    __syncthreads();
    #pragma unroll
    for (int off = 1; off < 1024; off <<= 1) {
        int v = (tid >= off) ? ps[tid - off] : 0;
        __syncthreads();
        ps[tid] += v;
        __syncthreads();
    }
    int running = ps[tid] - sum;
    for (int i = lo; i < hi; ++i) {
        g_cur[i] = running;
        running += g_cnt[i];
    }
}

__global__ void fill_kernel(const int* __restrict__ ei,
                            const int* __restrict__ et) {
    int e = blockIdx.x * blockDim.x + threadIdx.x;
    if (e >= N_EDGES) return;
    int s = __ldg(ei + e);
    int d = __ldg(ei + N_EDGES + e);
    int r = __ldg(et + e);
    int pos = atomicAdd(&g_cur[d], 1);
    g_eadj64[pos] = ((unsigned long long)(unsigned)s << 23)
                  | ((unsigned long long)(unsigned)r << 17)
                  | (unsigned long long)(unsigned)d;
}

// ---------------- relation conv + edge-weight table ----------------
__global__ void rel_kernel(const float* __restrict__ rel_x,
                           const int*   __restrict__ rel_ei,
                           const float* __restrict__ rel_ea,
                           const float* __restrict__ W_nn,
                           const float* __restrict__ b_nn) {
    __shared__ __align__(16) float h[R_REL * RF_REL];
    __shared__ __align__(16) float A[R_REL * R_REL];
    __shared__ float cnt[R_REL];
    int tid = threadIdx.x;  // 1024

    for (int i = tid; i < R_REL * RF_REL; i += 1024) { h[i] = rel_x[i]; A[i] = 0.f; }
    if (tid < R_REL) cnt[tid] = 0.f;
    __syncthreads();

    for (int e = tid; e < ER_REL; e += 1024) {
        int sr = rel_ei[e];
        int dr = rel_ei[ER_REL + e];
        float a = rel_ea[e];
        atomicAdd(&A[dr * R_REL + sr], a);
        atomicAdd(&cnt[dr], 1.0f);
    }
    __syncthreads();

    int r  = tid >> 4;
    int c4 = (tid & 15) * 4;
    float inv = 1.0f / fmaxf(cnt[r], 1.0f);

    #pragma unroll
    for (int it = 0; it < 2; ++it) {
        float4 acc = make_float4(0.f, 0.f, 0.f, 0.f);
        #pragma unroll 8
        for (int k = 0; k < R_REL; ++k) {
            float a = A[r * R_REL + k];
            float4 hv = *(const float4*)&h[k * RF_REL + c4];
            acc.x += a * hv.x; acc.y += a * hv.y;
            acc.z += a * hv.z; acc.w += a * hv.w;
        }
        __syncthreads();
        float4 hv = *(const float4*)&h[r * RF_REL + c4];
        hv.x = fmaxf(hv.x + acc.x * inv, 0.f);
        hv.y = fmaxf(hv.y + acc.y * inv, 0.f);
        hv.z = fmaxf(hv.z + acc.z * inv, 0.f);
        hv.w = fmaxf(hv.w + acc.w * inv, 0.f);
        *(float4*)&h[r * RF_REL + c4] = hv;
        __syncthreads();
    }

    for (int i = tid; i < RF_REL * DIM; i += 1024) A[i] = W_nn[i];
    __syncthreads();
    float4 acc = make_float4(b_nn[c4], b_nn[c4 + 1], b_nn[c4 + 2], b_nn[c4 + 3]);
    #pragma unroll 8
    for (int k = 0; k < RF_REL; ++k) {
        float hv = h[r * RF_REL + k];
        float4 wv = *(const float4*)&A[k * DIM + c4];
        acc.x += hv * wv.x; acc.y += hv * wv.y;
        acc.z += hv * wv.z; acc.w += hv * wv.w;
    }
    *(float4*)&g_wrel[r * DIM + c4] = acc;
}

// x0 = x_in @ fc1 -> fp16 mirror ONLY. (R8-proven layout.)
__global__ void proj_kernel(const float* __restrict__ x_in,
                            const float* __restrict__ fc1) {
    __shared__ __align__(16) float fs[F_IN * DIM];   // 32 KB
    __shared__ __align__(16) float is[64 * 64];      // 16 KB, swizzled
    int tid = threadIdx.x;
    for (int i = tid; i < F_IN * DIM; i += 256) fs[i] = fc1[i];

    int c4 = (tid & 15) * 4;
    int n4 = (tid >> 4) * 4;
    int sw = tid >> 4;
    int ntiles = (N_NODES + 63) / 64;

    for (int t = blockIdx.x; t < ntiles; t += gridDim.x) {
        int base = t * 64;
        float acc[4][4];
        #pragma unroll
        for (int j = 0; j < 4; ++j)
            #pragma unroll
            for (int i = 0; i < 4; ++i) acc[j][i] = 0.f;

        #pragma unroll
        for (int kb = 0; kb < F_IN; kb += 64) {
            __syncthreads();
            for (int i = tid; i < 64 * 64; i += 256) {
                int nn = i >> 6, k = i & 63;
                int n = base + nn;
                is[nn * 64 + (k ^ (nn >> 2))] =
                    (n < N_NODES) ? x_in[(size_t)n * F_IN + kb + k] : 0.f;
            }
            __syncthreads();
            #pragma unroll 4
            for (int kk = 0; kk < 64; ++kk) {
                float4 f = *(const float4*)&fs[(kb + kk) * DIM + c4];
                int ks = kk ^ sw;
                #pragma unroll
                for (int j = 0; j < 4; ++j) {
                    float iv = is[(n4 + j) * 64 + ks];
                    acc[j][0] += iv * f.x;
                    acc[j][1] += iv * f.y;
                    acc[j][2] += iv * f.z;
                    acc[j][3] += iv * f.w;
                }
            }
        }
        #pragma unroll
        for (int j = 0; j < 4; ++j) {
            int n = base + n4 + j;
            if (n < N_NODES) {
                __half2 h0 = __floats2half2_rn(acc[j][0], acc[j][1]);
                __half2 h1 = __floats2half2_rn(acc[j][2], acc[j][3]);
                uint2 p = make_uint2(*(uint32_t*)&h0, *(uint32_t*)&h1);
                *(uint2*)(g_x0h + (size_t)n * 32 + (c4 >> 1)) = p;
            }
        }
    }
}

// Sweep over dst-sorted edges: R8 shape (16-lane groups, 4-edge batches,
// 4 gathers in flight) + register accumulation across same-dst runs inside
// the batch. Flush = one red.v4 per lane, only on run change / batch end.
__global__ void sweep_kernel(int layer) {
    __shared__ __align__(16) float ws[R_REL * DIM];  // 16 KB
    for (int i = threadIdx.x; i < R_REL * DIM; i += blockDim.x) ws[i] = g_wrel[i];
    __syncthreads();

    const __half2* __restrict__ xh = (layer == 1) ? g_x0h : g_x1h;

    int G    = (gridDim.x * blockDim.x) >> 4;
    int g    = (blockIdx.x * blockDim.x + threadIdx.x) >> 4;
    int lane = threadIdx.x & 15;
    const int NB = N_EDGES / 4;   // 500000 batches

    for (int q = g; q < NB; q += G) {
        size_t e = (size_t)q * 4;
        ulonglong2 qa = __ldg((const ulonglong2*)(g_eadj64 + e));      // broadcast
        ulonglong2 qb = __ldg((const ulonglong2*)(g_eadj64 + e + 2));

        // 4 independent gathers in flight before any consumption
        uint2 p0 = __ldg((const uint2*)(xh + (size_t)(qa.x >> 23) * 32 + lane * 2));
        uint2 p1 = __ldg((const uint2*)(xh + (size_t)(qa.y >> 23) * 32 + lane * 2));
        uint2 p2 = __ldg((const uint2*)(xh + (size_t)(qb.x >> 23) * 32 + lane * 2));
        uint2 p3 = __ldg((const uint2*)(xh + (size_t)(qb.y >> 23) * 32 + lane * 2));

        int d0 = (int)(qa.x & 0x1FFFF), d1 = (int)(qa.y & 0x1FFFF);
        int d2 = (int)(qb.x & 0x1FFFF), d3 = (int)(qb.y & 0x1FFFF);

        const float* w0 = &ws[((unsigned)(qa.x >> 17) & 63u) * DIM + lane * 4];
        const float* w1 = &ws[((unsigned)(qa.y >> 17) & 63u) * DIM + lane * 4];
        const float* w2 = &ws[((unsigned)(qb.x >> 17) & 63u) * DIM + lane * 4];
        const float* w3 = &ws[((unsigned)(qb.y >> 17) & 63u) * DIM + lane * 4];

        float2 a0, a1; float4 wv, m, acc;

        a0 = __half22float2(*(__half2*)&p0.x); a1 = __half22float2(*(__half2*)&p0.y);
        wv = *(const float4*)w0;
        acc = make_float4(a0.x * wv.x, a0.y * wv.y, a1.x * wv.z, a1.y * wv.w);

        a0 = __half22float2(*(__half2*)&p1.x); a1 = __half22float2(*(__half2*)&p1.y);
        wv = *(const float4*)w1;
        m = make_float4(a0.x * wv.x, a0.y * wv.y, a1.x * wv.z, a1.y * wv.w);
        if (d1 != d0) {
            red_add_v4(g_agg + (size_t)d0 * DIM + lane * 4, acc);
            acc = m;
        } else {
            acc.x += m.x; acc.y += m.y; acc.z += m.z; acc.w += m.w;
        }

        a0 = __half22float2(*(__half2*)&p2.x); a1 = __half22float2(*(__half2*)&p2.y);
        wv = *(const float4*)w2;
        m = make_float4(a0.x * wv.x, a0.y * wv.y, a1.x * wv.z, a1.y * wv.w);
        if (d2 != d1) {
            red_add_v4(g_agg + (size_t)d1 * DIM + lane * 4, acc);
            acc = m;
        } else {
            acc.x += m.x; acc.y += m.y; acc.z += m.z; acc.w += m.w;
        }

        a0 = __half22float2(*(__half2*)&p3.x); a1 = __half22float2(*(__half2*)&p3.y);
        wv = *(const float4*)w3;
        m = make_float4(a0.x * wv.x, a0.y * wv.y, a1.x * wv.z, a1.y * wv.w);
        if (d3 != d2) {
            red_add_v4(g_agg + (size_t)d2 * DIM + lane * 4, acc);
            acc = m;
        } else {
            acc.x += m.x; acc.y += m.y; acc.z += m.z; acc.w += m.w;
        }

        red_add_v4(g_agg + (size_t)d3 * DIM + lane * 4, acc);
    }
}

// x_out = tanh(agg / max(deg,1) + b). layer1 -> fp16 mirror; layer2 -> fp32 g_x0.
__global__ void finish_kernel(const float* __restrict__ b,
                              int layer, int zero_agg) {
    int i = blockIdx.x * blockDim.x + threadIdx.x;
    if (i >= N_NODES * (DIM / 4)) return;
    int n = i >> 4, c4 = (i & 15) * 4;
    float4 v = ((const float4*)g_agg)[i];
    int d = g_cnt[n];
    float inv = 1.0f / (float)(d > 0 ? d : 1);
    float4 bb = *(const float4*)(b + c4);
    v.x = tanhf(v.x * inv + bb.x);
    v.y = tanhf(v.y * inv + bb.y);
    v.z = tanhf(v.z * inv + bb.z);
    v.w = tanhf(v.w * inv + bb.w);
    if (layer == 1) {
        __half2 h0 = __floats2half2_rn(v.x, v.y);
        __half2 h1 = __floats2half2_rn(v.z, v.w);
        uint2 p = make_uint2(*(uint32_t*)&h0, *(uint32_t*)&h1);
        *(uint2*)(g_x1h + (size_t)n * 32 + (c4 >> 1)) = p;
    } else {
        ((float4*)g_x0)[i] = v;
    }
    if (zero_agg) ((float4*)g_agg)[i] = make_float4(0.f, 0.f, 0.f, 0.f);
}

// out = x2 @ fc2_w + fc2_b   (x2 in g_x0).  16 nodes per block.
__global__ void out_kernel(const float* __restrict__ fc2w,
                           const float* __restrict__ fc2b,
                           float* __restrict__ out) {
    __shared__ float ws[DIM * NCLS];
    __shared__ float xs[16 * DIM];
    int tid = threadIdx.x;
    for (int i = tid; i < DIM * NCLS; i += 256) ws[i] = fc2w[i];
    int base = blockIdx.x * 16;
    for (int i = tid; i < 16 * DIM; i += 256) xs[i] = g_x0[(size_t)base * DIM + i];
    __syncthreads();
    int nl = tid >> 4, k = tid & 15;
    float acc = fc2b[k];
    #pragma unroll
    for (int c = 0; c < DIM; ++c)
        acc += xs[nl * DIM + c] * ws[c * NCLS + k];
    out[(size_t)(base + nl) * NCLS + k] = acc;
}

// ---------------- launch ----------------
extern "C" void kernel_launch(void* const* d_in, const int* in_sizes, int n_in,
                              void* d_out, int out_size) {
    const float* x_in   = (const float*)d_in[0];
    const float* rel_x  = (const float*)d_in[1];
    const int*   ei     = (const int*)  d_in[2];
    const int*   et     = (const int*)  d_in[3];
    const int*   rel_ei = (const int*)  d_in[4];
    const float* rel_ea = (const float*)d_in[5];
    const float* fc1    = (const float*)d_in[6];
    const float* W_nn   = (const float*)d_in[7];
    const float* b_nn   = (const float*)d_in[8];
    const float* b1     = (const float*)d_in[9];
    const float* b2     = (const float*)d_in[10];
    const float* fc2w   = (const float*)d_in[11];
    const float* fc2b   = (const float*)d_in[12];
    float* out = (float*)d_out;

    // dst-sorted edge list + degrees (+ zeroed agg)
    zero_kernel<<<(N_NODES * DIM / 4 + 255) / 256, 256>>>();
    count_kernel<<<(N_EDGES + 255) / 256, 256>>>(ei + N_EDGES);
    scan_kernel<<<1, 1024>>>();
    fill_kernel<<<(N_EDGES + 255) / 256, 256>>>(ei, et);

    rel_kernel<<<1, 1024>>>(rel_x, rel_ei, rel_ea, W_nn, b_nn);
    proj_kernel<<<1184, 256>>>(x_in, fc1);

    sweep_kernel<<<2048, 256>>>(1);
    finish_kernel<<<(N_NODES * 16 + 255) / 256, 256>>>(b1, 1, /*zero_agg=*/1);

    sweep_kernel<<<2048, 256>>>(2);
    finish_kernel<<<(N_NODES * 16 + 255) / 256, 256>>>(b2, 2, /*zero_agg=*/0);

    out_kernel<<<N_NODES / 16, 256>>>(fc2w, fc2b, out);
}

// round 10
// speedup vs baseline: 1.0500x; 1.0500x over previous
#include <cuda_runtime.h>
#include <cuda_fp16.h>
#include <cstdint>

#define N_NODES 100000
#define N_EDGES 2000000
#define DIM     64
#define F_IN    128
#define R_REL   64
#define ER_REL  2048
#define RF_REL  64
#define NCLS    16

// ---------------- scratch (static device memory; no allocations) ----------------
__device__ __align__(16) float g_x0[N_NODES * DIM];        // x2 (fp32, for out_kernel)
__device__ __align__(16) float g_agg[N_NODES * DIM];       // scatter accumulator
__device__ __align__(16) __half2 g_x0h[N_NODES * DIM / 2]; // fp16 mirror of x0 (proj out)
__device__ __align__(16) __half2 g_x1h[N_NODES * DIM / 2]; // fp16 mirror of x1 (conv1 out)
__device__ int g_deg[N_NODES];
__device__ __align__(16) float g_wrel[R_REL * DIM];        // per-relation edge weights
__device__ __align__(16) unsigned g_pk[N_EDGES];           // packed (src<<6)|etype

// ---------------- helpers ----------------
__device__ __forceinline__ void red_add_v4(float* addr, float a, float b, float c, float d) {
    asm volatile("red.global.add.v4.f32 [%0], {%1, %2, %3, %4};"
                 :: "l"(addr), "f"(a), "f"(b), "f"(c), "f"(d)
                 : "memory");
}
__device__ __forceinline__ void red_add_s32(int* addr, int v) {
    asm volatile("red.global.add.s32 [%0], %1;" :: "l"(addr), "r"(v) : "memory");
}

// ---------------- fused init: pack edges + zero agg + zero deg ----------------
__global__ void init_kernel(const int* __restrict__ src,
                            const int* __restrict__ et) {
    int i = blockIdx.x * blockDim.x + threadIdx.x;
    if (i < N_EDGES)
        g_pk[i] = ((unsigned)__ldg(src + i) << 6) | (unsigned)__ldg(et + i);
    if (i < N_NODES * DIM / 4)
        ((float4*)g_agg)[i] = make_float4(0.f, 0.f, 0.f, 0.f);
    if (i < N_NODES) g_deg[i] = 0;
}

// Relation conv x2 + w_rel = relu-chain(rel_x) @ W_nn + b_nn (GEMM form).
__global__ void rel_kernel(const float* __restrict__ rel_x,
                           const int*   __restrict__ rel_ei,
                           const float* __restrict__ rel_ea,
                           const float* __restrict__ W_nn,
                           const float* __restrict__ b_nn) {
    __shared__ __align__(16) float h[R_REL * RF_REL];
    __shared__ __align__(16) float A[R_REL * R_REL];
    __shared__ float cnt[R_REL];
    int tid = threadIdx.x;  // 1024

    for (int i = tid; i < R_REL * RF_REL; i += 1024) { h[i] = rel_x[i]; A[i] = 0.f; }
    if (tid < R_REL) cnt[tid] = 0.f;
    __syncthreads();

    for (int e = tid; e < ER_REL; e += 1024) {
        int sr = rel_ei[e];
        int dr = rel_ei[ER_REL + e];
        float a = rel_ea[e];
        atomicAdd(&A[dr * R_REL + sr], a);
        atomicAdd(&cnt[dr], 1.0f);
    }
    __syncthreads();

    int r  = tid >> 4;
    int c4 = (tid & 15) * 4;
    float inv = 1.0f / fmaxf(cnt[r], 1.0f);

    #pragma unroll
    for (int it = 0; it < 2; ++it) {
        float4 acc = make_float4(0.f, 0.f, 0.f, 0.f);
        #pragma unroll 8
        for (int k = 0; k < R_REL; ++k) {
            float a = A[r * R_REL + k];
            float4 hv = *(const float4*)&h[k * RF_REL + c4];
            acc.x += a * hv.x; acc.y += a * hv.y;
            acc.z += a * hv.z; acc.w += a * hv.w;
        }
        __syncthreads();
        float4 hv = *(const float4*)&h[r * RF_REL + c4];
        hv.x = fmaxf(hv.x + acc.x * inv, 0.f);
        hv.y = fmaxf(hv.y + acc.y * inv, 0.f);
        hv.z = fmaxf(hv.z + acc.z * inv, 0.f);
        hv.w = fmaxf(hv.w + acc.w * inv, 0.f);
        *(float4*)&h[r * RF_REL + c4] = hv;
        __syncthreads();
    }

    for (int i = tid; i < RF_REL * DIM; i += 1024) A[i] = W_nn[i];
    __syncthreads();
    float4 acc = make_float4(b_nn[c4], b_nn[c4 + 1], b_nn[c4 + 2], b_nn[c4 + 3]);
    #pragma unroll 8
    for (int k = 0; k < RF_REL; ++k) {
        float hv = h[r * RF_REL + k];
        float4 wv = *(const float4*)&A[k * DIM + c4];
        acc.x += hv * wv.x; acc.y += hv * wv.y;
        acc.z += hv * wv.z; acc.w += hv * wv.w;
    }
    *(float4*)&g_wrel[r * DIM + c4] = acc;
}

// x0 = x_in @ fc1 -> fp16 mirror only. 128-node tiles, 4 nodes x 8 cols/thread
// (higher FFMA fraction per issue slot than the 4x4 tile).
__global__ void proj_kernel(const float* __restrict__ x_in,
                            const float* __restrict__ fc1) {
    __shared__ __align__(16) float fs[F_IN * DIM];   // 32 KB
    __shared__ __align__(16) float is[128 * 32];     // 16 KB, swizzled
    int tid = threadIdx.x;  // 256
    for (int i = tid; i < F_IN * DIM; i += 256) fs[i] = fc1[i];

    int c8 = (tid & 7) * 8;      // 8 output cols
    int n4 = (tid >> 3) * 4;     // 4 nodes
    int sw = tid >> 3;           // == row>>2 for rows n4..n4+3
    int base = blockIdx.x * 128;

    float acc[4][8];
    #pragma unroll
    for (int j = 0; j < 4; ++j)
        #pragma unroll
        for (int i = 0; i < 8; ++i) acc[j][i] = 0.f;

    #pragma unroll
    for (int kb = 0; kb < F_IN; kb += 32) {
        __syncthreads();
        for (int i = tid; i < 128 * 32; i += 256) {
            int nn = i >> 5, k = i & 31;
            int n = base + nn;
            is[nn * 32 + (k ^ ((nn >> 2) & 31))] =
                (n < N_NODES) ? x_in[(size_t)n * F_IN + kb + k] : 0.f;
        }
        __syncthreads();
        #pragma unroll 4
        for (int kk = 0; kk < 32; ++kk) {
            float4 f0 = *(const float4*)&fs[(kb + kk) * DIM + c8];
            float4 f1 = *(const float4*)&fs[(kb + kk) * DIM + c8 + 4];
            int ks = kk ^ (sw & 31);
            #pragma unroll
            for (int j = 0; j < 4; ++j) {
                float iv = is[(n4 + j) * 32 + ks];
                acc[j][0] += iv * f0.x; acc[j][1] += iv * f0.y;
                acc[j][2] += iv * f0.z; acc[j][3] += iv * f0.w;
                acc[j][4] += iv * f1.x; acc[j][5] += iv * f1.y;
                acc[j][6] += iv * f1.z; acc[j][7] += iv * f1.w;
            }
        }
    }
    #pragma unroll
    for (int j = 0; j < 4; ++j) {
        int n = base + n4 + j;
        if (n < N_NODES) {
            __half2 h0 = __floats2half2_rn(acc[j][0], acc[j][1]);
            __half2 h1 = __floats2half2_rn(acc[j][2], acc[j][3]);
            __half2 h2 = __floats2half2_rn(acc[j][4], acc[j][5]);
            __half2 h3 = __floats2half2_rn(acc[j][6], acc[j][7]);
            uint4 p = make_uint4(*(uint32_t*)&h0, *(uint32_t*)&h1,
                                 *(uint32_t*)&h2, *(uint32_t*)&h3);
            *(uint4*)(g_x0h + (size_t)n * 32 + (c8 >> 1)) = p;
        }
    }
}

// Push edge sweep, 4-edge pipelined (R8-proven).
__global__ void edge_kernel(const int* __restrict__ dst,
                            int which_x, int count_deg) {
    __shared__ __align__(16) float ws[R_REL * DIM];  // 16 KB
    for (int i = threadIdx.x; i < R_REL * DIM; i += blockDim.x) ws[i] = g_wrel[i];
    __syncthreads();

    const __half2* __restrict__ xh = which_x ? g_x1h : g_x0h;

    int G    = (gridDim.x * blockDim.x) >> 4;
    int g    = (blockIdx.x * blockDim.x + threadIdx.x) >> 4;
    int lane = threadIdx.x & 15;
    const int NQUADS = N_EDGES / 4;

    for (int q = g; q < NQUADS; q += G) {
        int e = q * 4;
        uint4 pk = __ldg((const uint4*)(g_pk + e));   // broadcast within group
        uint4 dd = *(const uint4*)(dst + e);          // broadcast within group

        uint2 p0 = __ldg((const uint2*)(xh + (size_t)(pk.x >> 6) * 32 + lane * 2));
        uint2 p1 = __ldg((const uint2*)(xh + (size_t)(pk.y >> 6) * 32 + lane * 2));
        uint2 p2 = __ldg((const uint2*)(xh + (size_t)(pk.z >> 6) * 32 + lane * 2));
        uint2 p3 = __ldg((const uint2*)(xh + (size_t)(pk.w >> 6) * 32 + lane * 2));

        unsigned pks[4] = {pk.x, pk.y, pk.z, pk.w};
        unsigned dds[4] = {dd.x, dd.y, dd.z, dd.w};
        uint2    pps[4] = {p0, p1, p2, p3};
        #pragma unroll
        for (int j = 0; j < 4; ++j) {
            float2 f0 = __half22float2(*(__half2*)&pps[j].x);
            float2 f1 = __half22float2(*(__half2*)&pps[j].y);
            float4 wv = *(const float4*)&ws[(pks[j] & 63u) * DIM + lane * 4];
            red_add_v4(g_agg + (size_t)dds[j] * DIM + lane * 4,
                       f0.x * wv.x, f0.y * wv.y, f1.x * wv.z, f1.y * wv.w);
            if (count_deg && lane == 0) red_add_s32(&g_deg[dds[j]], 1);
        }
    }
}

// x_out = tanh(agg / max(deg,1) + b). layer1 -> fp16 mirror; layer2 -> fp32 g_x0.
__global__ void finish_kernel(const float* __restrict__ b,
                              int layer, int zero_agg) {
    int i = blockIdx.x * blockDim.x + threadIdx.x;
    if (i >= N_NODES * (DIM / 4)) return;
    int n = i >> 4, c4 = (i & 15) * 4;
    float4 v = ((const float4*)g_agg)[i];
    int d = g_deg[n];
    float inv = 1.0f / (float)(d > 0 ? d : 1);
    float4 bb = *(const float4*)(b + c4);
    v.x = tanhf(v.x * inv + bb.x);
    v.y = tanhf(v.y * inv + bb.y);
    v.z = tanhf(v.z * inv + bb.z);
    v.w = tanhf(v.w * inv + bb.w);
    if (layer == 1) {
        __half2 h0 = __floats2half2_rn(v.x, v.y);
        __half2 h1 = __floats2half2_rn(v.z, v.w);
        uint2 p = make_uint2(*(uint32_t*)&h0, *(uint32_t*)&h1);
        *(uint2*)(g_x1h + (size_t)n * 32 + (c4 >> 1)) = p;
    } else {
        ((float4*)g_x0)[i] = v;
    }
    if (zero_agg) ((float4*)g_agg)[i] = make_float4(0.f, 0.f, 0.f, 0.f);
}

// out = x2 @ fc2_w + fc2_b   (x2 in g_x0).  16 nodes per block.
__global__ void out_kernel(const float* __restrict__ fc2w,
                           const float* __restrict__ fc2b,
                           float* __restrict__ out) {
    __shared__ float ws[DIM * NCLS];
    __shared__ float xs[16 * DIM];
    int tid = threadIdx.x;
    for (int i = tid; i < DIM * NCLS; i += 256) ws[i] = fc2w[i];
    int base = blockIdx.x * 16;
    for (int i = tid; i < 16 * DIM; i += 256) xs[i] = g_x0[(size_t)base * DIM + i];
    __syncthreads();
    int nl = tid >> 4, k = tid & 15;
    float acc = fc2b[k];
    #pragma unroll
    for (int c = 0; c < DIM; ++c)
        acc += xs[nl * DIM + c] * ws[c * NCLS + k];
    out[(size_t)(base + nl) * NCLS + k] = acc;
}

// ---------------- launch ----------------
extern "C" void kernel_launch(void* const* d_in, const int* in_sizes, int n_in,
                              void* d_out, int out_size) {
    const float* x_in   = (const float*)d_in[0];
    const float* rel_x  = (const float*)d_in[1];
    const int*   ei     = (const int*)  d_in[2];
    const int*   et     = (const int*)  d_in[3];
    const int*   rel_ei = (const int*)  d_in[4];
    const float* rel_ea = (const float*)d_in[5];
    const float* fc1    = (const float*)d_in[6];
    const float* W_nn   = (const float*)d_in[7];
    const float* b_nn   = (const float*)d_in[8];
    const float* b1     = (const float*)d_in[9];
    const float* b2     = (const float*)d_in[10];
    const float* fc2w   = (const float*)d_in[11];
    const float* fc2b   = (const float*)d_in[12];
    float* out = (float*)d_out;

    // Launch order chosen so edge_kernel (conv1) is the 4th launch -> profiled.
    init_kernel<<<(N_EDGES + 255) / 256, 256>>>(ei, et);              // 1
    rel_kernel<<<1, 1024>>>(rel_x, rel_ei, rel_ea, W_nn, b_nn);       // 2
    proj_kernel<<<(N_NODES + 127) / 128, 256>>>(x_in, fc1);           // 3

    edge_kernel<<<2048, 256>>>(ei + N_EDGES, 0, /*count_deg=*/1);     // 4 <- profiled
    finish_kernel<<<(N_NODES * 16 + 255) / 256, 256>>>(b1, 1, 1);     // 5

    edge_kernel<<<2048, 256>>>(ei + N_EDGES, 1, /*count_deg=*/0);     // 6
    finish_kernel<<<(N_NODES * 16 + 255) / 256, 256>>>(b2, 2, 0);     // 7

    out_kernel<<<N_NODES / 16, 256>>>(fc2w, fc2b, out);               // 8
}

// round 11
// speedup vs baseline: 1.1386x; 1.0843x over previous
#include <cuda_runtime.h>
#include <cuda_fp16.h>
#include <cstdint>

#define N_NODES 100000
#define N_EDGES 2000000
#define DIM     64
#define F_IN    128
#define R_REL   64
#define ER_REL  2048
#define RF_REL  64
#define NCLS    16

// ---------------- scratch (static device memory; no allocations) ----------------
__device__ __align__(16) float g_agg[N_NODES * DIM];       // scatter accumulator
__device__ __align__(16) __half2 g_x0h[N_NODES * DIM / 2]; // fp16 mirror of x0 (proj out)
__device__ __align__(16) __half2 g_x1h[N_NODES * DIM / 2]; // fp16 mirror of x1 (conv1 out)
__device__ int g_deg[N_NODES];
__device__ __align__(16) float g_wrel[R_REL * DIM];        // per-relation edge weights
__device__ __align__(16) unsigned g_pk[N_EDGES];           // packed (src<<6)|etype

// ---------------- helpers ----------------
__device__ __forceinline__ void red_add_v4(float* addr, float a, float b, float c, float d) {
    asm volatile("red.global.add.v4.f32 [%0], {%1, %2, %3, %4};"
                 :: "l"(addr), "f"(a), "f"(b), "f"(c), "f"(d)
                 : "memory");
}
__device__ __forceinline__ void red_add_s32(int* addr, int v) {
    asm volatile("red.global.add.s32 [%0], %1;" :: "l"(addr), "r"(v) : "memory");
}

// ---------------- fused init: pack edges + zero agg + zero deg ----------------
__global__ void init_kernel(const int* __restrict__ src,
                            const int* __restrict__ et) {
    int i = blockIdx.x * blockDim.x + threadIdx.x;
    if (i < N_EDGES)
        g_pk[i] = ((unsigned)__ldg(src + i) << 6) | (unsigned)__ldg(et + i);
    if (i < N_NODES * DIM / 4)
        ((float4*)g_agg)[i] = make_float4(0.f, 0.f, 0.f, 0.f);
    if (i < N_NODES) g_deg[i] = 0;
}

// Relation conv x2 + w_rel = relu-chain(rel_x) @ W_nn + b_nn (GEMM form).
__global__ void rel_kernel(const float* __restrict__ rel_x,
                           const int*   __restrict__ rel_ei,
                           const float* __restrict__ rel_ea,
                           const float* __restrict__ W_nn,
                           const float* __restrict__ b_nn) {
    __shared__ __align__(16) float h[R_REL * RF_REL];
    __shared__ __align__(16) float A[R_REL * R_REL];
    __shared__ float cnt[R_REL];
    int tid = threadIdx.x;  // 1024

    for (int i = tid; i < R_REL * RF_REL; i += 1024) { h[i] = rel_x[i]; A[i] = 0.f; }
    if (tid < R_REL) cnt[tid] = 0.f;
    __syncthreads();

    for (int e = tid; e < ER_REL; e += 1024) {
        int sr = rel_ei[e];
        int dr = rel_ei[ER_REL + e];
        float a = rel_ea[e];
        atomicAdd(&A[dr * R_REL + sr], a);
        atomicAdd(&cnt[dr], 1.0f);
    }
    __syncthreads();

    int r  = tid >> 4;
    int c4 = (tid & 15) * 4;
    float inv = 1.0f / fmaxf(cnt[r], 1.0f);

    #pragma unroll
    for (int it = 0; it < 2; ++it) {
        float4 acc = make_float4(0.f, 0.f, 0.f, 0.f);
        #pragma unroll 8
        for (int k = 0; k < R_REL; ++k) {
            float a = A[r * R_REL + k];
            float4 hv = *(const float4*)&h[k * RF_REL + c4];
            acc.x += a * hv.x; acc.y += a * hv.y;
            acc.z += a * hv.z; acc.w += a * hv.w;
        }
        __syncthreads();
        float4 hv = *(const float4*)&h[r * RF_REL + c4];
        hv.x = fmaxf(hv.x + acc.x * inv, 0.f);
        hv.y = fmaxf(hv.y + acc.y * inv, 0.f);
        hv.z = fmaxf(hv.z + acc.z * inv, 0.f);
        hv.w = fmaxf(hv.w + acc.w * inv, 0.f);
        *(float4*)&h[r * RF_REL + c4] = hv;
        __syncthreads();
    }

    for (int i = tid; i < RF_REL * DIM; i += 1024) A[i] = W_nn[i];
    __syncthreads();
    float4 acc = make_float4(b_nn[c4], b_nn[c4 + 1], b_nn[c4 + 2], b_nn[c4 + 3]);
    #pragma unroll 8
    for (int k = 0; k < RF_REL; ++k) {
        float hv = h[r * RF_REL + k];
        float4 wv = *(const float4*)&A[k * DIM + c4];
        acc.x += hv * wv.x; acc.y += hv * wv.y;
        acc.z += hv * wv.z; acc.w += hv * wv.w;
    }
    *(float4*)&g_wrel[r * DIM + c4] = acc;
}

// x0 = x_in @ fc1 -> fp16 mirror only. R8-proven: 64-node tiles, 4x4 register
// tile, swizzled input, persistent 1184-block grid.
__global__ void proj_kernel(const float* __restrict__ x_in,
                            const float* __restrict__ fc1) {
    __shared__ __align__(16) float fs[F_IN * DIM];   // 32 KB
    __shared__ __align__(16) float is[64 * 64];      // 16 KB, swizzled
    int tid = threadIdx.x;
    for (int i = tid; i < F_IN * DIM; i += 256) fs[i] = fc1[i];

    int c4 = (tid & 15) * 4;
    int n4 = (tid >> 4) * 4;
    int sw = tid >> 4;
    int ntiles = (N_NODES + 63) / 64;

    for (int t = blockIdx.x; t < ntiles; t += gridDim.x) {
        int base = t * 64;
        float acc[4][4];
        #pragma unroll
        for (int j = 0; j < 4; ++j)
            #pragma unroll
            for (int i = 0; i < 4; ++i) acc[j][i] = 0.f;

        #pragma unroll
        for (int kb = 0; kb < F_IN; kb += 64) {
            __syncthreads();
            for (int i = tid; i < 64 * 64; i += 256) {
                int nn = i >> 6, k = i & 63;
                int n = base + nn;
                is[nn * 64 + (k ^ (nn >> 2))] =
                    (n < N_NODES) ? x_in[(size_t)n * F_IN + kb + k] : 0.f;
            }
            __syncthreads();
            #pragma unroll 4
            for (int kk = 0; kk < 64; ++kk) {
                float4 f = *(const float4*)&fs[(kb + kk) * DIM + c4];
                int ks = kk ^ sw;
                #pragma unroll
                for (int j = 0; j < 4; ++j) {
                    float iv = is[(n4 + j) * 64 + ks];
                    acc[j][0] += iv * f.x;
                    acc[j][1] += iv * f.y;
                    acc[j][2] += iv * f.z;
                    acc[j][3] += iv * f.w;
                }
            }
        }
        #pragma unroll
        for (int j = 0; j < 4; ++j) {
            int n = base + n4 + j;
            if (n < N_NODES) {
                __half2 h0 = __floats2half2_rn(acc[j][0], acc[j][1]);
                __half2 h1 = __floats2half2_rn(acc[j][2], acc[j][3]);
                uint2 p = make_uint2(*(uint32_t*)&h0, *(uint32_t*)&h1);
                *(uint2*)(g_x0h + (size_t)n * 32 + (c4 >> 1)) = p;
            }
        }
    }
}

// Push edge sweep, 4-edge pipelined (R8-proven).
__global__ void edge_kernel(const int* __restrict__ dst,
                            int which_x, int count_deg) {
    __shared__ __align__(16) float ws[R_REL * DIM];  // 16 KB
    for (int i = threadIdx.x; i < R_REL * DIM; i += blockDim.x) ws[i] = g_wrel[i];
    __syncthreads();

    const __half2* __restrict__ xh = which_x ? g_x1h : g_x0h;

    int G    = (gridDim.x * blockDim.x) >> 4;
    int g    = (blockIdx.x * blockDim.x + threadIdx.x) >> 4;
    int lane = threadIdx.x & 15;
    const int NQUADS = N_EDGES / 4;

    for (int q = g; q < NQUADS; q += G) {
        int e = q * 4;
        uint4 pk = __ldg((const uint4*)(g_pk + e));   // broadcast within group
        uint4 dd = *(const uint4*)(dst + e);          // broadcast within group

        uint2 p0 = __ldg((const uint2*)(xh + (size_t)(pk.x >> 6) * 32 + lane * 2));
        uint2 p1 = __ldg((const uint2*)(xh + (size_t)(pk.y >> 6) * 32 + lane * 2));
        uint2 p2 = __ldg((const uint2*)(xh + (size_t)(pk.z >> 6) * 32 + lane * 2));
        uint2 p3 = __ldg((const uint2*)(xh + (size_t)(pk.w >> 6) * 32 + lane * 2));

        unsigned pks[4] = {pk.x, pk.y, pk.z, pk.w};
        unsigned dds[4] = {dd.x, dd.y, dd.z, dd.w};
        uint2    pps[4] = {p0, p1, p2, p3};
        #pragma unroll
        for (int j = 0; j < 4; ++j) {
            float2 f0 = __half22float2(*(__half2*)&pps[j].x);
            float2 f1 = __half22float2(*(__half2*)&pps[j].y);
            float4 wv = *(const float4*)&ws[(pks[j] & 63u) * DIM + lane * 4];
            red_add_v4(g_agg + (size_t)dds[j] * DIM + lane * 4,
                       f0.x * wv.x, f0.y * wv.y, f1.x * wv.z, f1.y * wv.w);
            if (count_deg && lane == 0) red_add_s32(&g_deg[dds[j]], 1);
        }
    }
}

// finish (layer 1 only): x1 = tanh(agg/deg + b1) -> fp16 mirror; re-zero agg.
__global__ void finish_kernel(const float* __restrict__ b) {
    int i = blockIdx.x * blockDim.x + threadIdx.x;
    if (i >= N_NODES * (DIM / 4)) return;
    int n = i >> 4, c4 = (i & 15) * 4;
    float4 v = ((const float4*)g_agg)[i];
    int d = g_deg[n];
    float inv = 1.0f / (float)(d > 0 ? d : 1);
    float4 bb = *(const float4*)(b + c4);
    v.x = tanhf(v.x * inv + bb.x);
    v.y = tanhf(v.y * inv + bb.y);
    v.z = tanhf(v.z * inv + bb.z);
    v.w = tanhf(v.w * inv + bb.w);
    __half2 h0 = __floats2half2_rn(v.x, v.y);
    __half2 h1 = __floats2half2_rn(v.z, v.w);
    uint2 p = make_uint2(*(uint32_t*)&h0, *(uint32_t*)&h1);
    *(uint2*)(g_x1h + (size_t)n * 32 + (c4 >> 1)) = p;
    ((float4*)g_agg)[i] = make_float4(0.f, 0.f, 0.f, 0.f);
}

// Fused finish2 + out:  out = tanh(agg/deg + b2) @ fc2_w + fc2_b.
// 16 nodes per block; x2 never hits global memory.
__global__ void out_kernel(const float* __restrict__ b2,
                           const float* __restrict__ fc2w,
                           const float* __restrict__ fc2b,
                           float* __restrict__ out) {
    __shared__ float ws[DIM * NCLS];  // 4 KB
    __shared__ float xs[16 * DIM];    // 4 KB
    int tid = threadIdx.x;
    for (int i = tid; i < DIM * NCLS; i += 256) ws[i] = fc2w[i];

    int base = blockIdx.x * 16;
    // each thread computes 4 tanh'd features: node = tid>>4, cols = (tid&15)*4
    {
        int nl = tid >> 4, c4 = (tid & 15) * 4;
        int n = base + nl;
        float4 v = *(const float4*)&g_agg[(size_t)n * DIM + c4];
        int d = g_deg[n];
        float inv = 1.0f / (float)(d > 0 ? d : 1);
        float4 bb = *(const float4*)(b2 + c4);
        v.x = tanhf(v.x * inv + bb.x);
        v.y = tanhf(v.y * inv + bb.y);
        v.z = tanhf(v.z * inv + bb.z);
        v.w = tanhf(v.w * inv + bb.w);
        *(float4*)&xs[nl * DIM + c4] = v;
    }
    __syncthreads();

    int nl = tid >> 4, k = tid & 15;
    float acc = fc2b[k];
    #pragma unroll
    for (int c = 0; c < DIM; ++c)
        acc += xs[nl * DIM + c] * ws[c * NCLS + k];
    out[(size_t)(base + nl) * NCLS + k] = acc;
}

// ---------------- launch ----------------
extern "C" void kernel_launch(void* const* d_in, const int* in_sizes, int n_in,
                              void* d_out, int out_size) {
    const float* x_in   = (const float*)d_in[0];
    const float* rel_x  = (const float*)d_in[1];
    const int*   ei     = (const int*)  d_in[2];
    const int*   et     = (const int*)  d_in[3];
    const int*   rel_ei = (const int*)  d_in[4];
    const float* rel_ea = (const float*)d_in[5];
    const float* fc1    = (const float*)d_in[6];
    const float* W_nn   = (const float*)d_in[7];
    const float* b_nn   = (const float*)d_in[8];
    const float* b1     = (const float*)d_in[9];
    const float* b2     = (const float*)d_in[10];
    const float* fc2w   = (const float*)d_in[11];
    const float* fc2b   = (const float*)d_in[12];
    float* out = (float*)d_out;

    // edge_kernel (conv1) kept as 4th launch -> profiled.
    init_kernel<<<(N_EDGES + 255) / 256, 256>>>(ei, et);              // 1
    rel_kernel<<<1, 1024>>>(rel_x, rel_ei, rel_ea, W_nn, b_nn);       // 2
    proj_kernel<<<1184, 256>>>(x_in, fc1);                            // 3

    edge_kernel<<<2048, 256>>>(ei + N_EDGES, 0, /*count_deg=*/1);     // 4 <- profiled
    finish_kernel<<<(N_NODES * 16 + 255) / 256, 256>>>(b1);           // 5

    edge_kernel<<<2048, 256>>>(ei + N_EDGES, 1, /*count_deg=*/0);     // 6
    out_kernel<<<N_NODES / 16, 256>>>(b2, fc2w, fc2b, out);           // 7
}

// round 12
// speedup vs baseline: 1.1882x; 1.0436x over previous
#include <cuda_runtime.h>
#include <cuda_fp16.h>
#include <cstdint>

#define N_NODES 100000
#define N_EDGES 2000000
#define DIM     64
#define F_IN    128
#define R_REL   64
#define ER_REL  2048
#define RF_REL  64
#define NCLS    16

// ---------------- scratch (static device memory; no allocations) ----------------
__device__ __align__(16) float g_agg[N_NODES * DIM];       // scatter accumulator
__device__ __align__(16) __half2 g_x0h[N_NODES * DIM / 2]; // fp16 mirror of x0 (proj out)
__device__ __align__(16) __half2 g_x1h[N_NODES * DIM / 2]; // fp16 mirror of x1 (conv1 out)
__device__ int g_deg[N_NODES];
__device__ __align__(16) float g_wrel[R_REL * DIM];        // per-relation edge weights
__device__ __align__(16) unsigned g_pk[N_EDGES];           // packed (src<<6)|etype

// ---------------- helpers ----------------
__device__ __forceinline__ void red_add_v4(float* addr, float a, float b, float c, float d) {
    asm volatile("red.global.add.v4.f32 [%0], {%1, %2, %3, %4};"
                 :: "l"(addr), "f"(a), "f"(b), "f"(c), "f"(d)
                 : "memory");
}
__device__ __forceinline__ void red_add_s32(int* addr, int v) {
    asm volatile("red.global.add.s32 [%0], %1;" :: "l"(addr), "r"(v) : "memory");
}
__device__ __forceinline__ void mma16816(float* d, const unsigned* a, const unsigned* b) {
    asm volatile("mma.sync.aligned.m16n8k16.row.col.f32.f16.f16.f32 "
                 "{%0,%1,%2,%3}, {%4,%5,%6,%7}, {%8,%9}, {%0,%1,%2,%3};"
                 : "+f"(d[0]), "+f"(d[1]), "+f"(d[2]), "+f"(d[3])
                 : "r"(a[0]), "r"(a[1]), "r"(a[2]), "r"(a[3]),
                   "r"(b[0]), "r"(b[1]));
}

// ---------------- fused init: pack edges + zero agg + zero deg ----------------
__global__ void init_kernel(const int* __restrict__ src,
                            const int* __restrict__ et) {
    int i = blockIdx.x * blockDim.x + threadIdx.x;
    if (i < N_EDGES)
        g_pk[i] = ((unsigned)__ldg(src + i) << 6) | (unsigned)__ldg(et + i);
    if (i < N_NODES * DIM / 4)
        ((float4*)g_agg)[i] = make_float4(0.f, 0.f, 0.f, 0.f);
    if (i < N_NODES) g_deg[i] = 0;
}

// Relation conv x2 + w_rel = relu-chain(rel_x) @ W_nn + b_nn (GEMM form).
__global__ void rel_kernel(const float* __restrict__ rel_x,
                           const int*   __restrict__ rel_ei,
                           const float* __restrict__ rel_ea,
                           const float* __restrict__ W_nn,
                           const float* __restrict__ b_nn) {
    __shared__ __align__(16) float h[R_REL * RF_REL];
    __shared__ __align__(16) float A[R_REL * R_REL];
    __shared__ float cnt[R_REL];
    int tid = threadIdx.x;  // 1024

    for (int i = tid; i < R_REL * RF_REL; i += 1024) { h[i] = rel_x[i]; A[i] = 0.f; }
    if (tid < R_REL) cnt[tid] = 0.f;
    __syncthreads();

    for (int e = tid; e < ER_REL; e += 1024) {
        int sr = rel_ei[e];
        int dr = rel_ei[ER_REL + e];
        float a = rel_ea[e];
        atomicAdd(&A[dr * R_REL + sr], a);
        atomicAdd(&cnt[dr], 1.0f);
    }
    __syncthreads();

    int r  = tid >> 4;
    int c4 = (tid & 15) * 4;
    float inv = 1.0f / fmaxf(cnt[r], 1.0f);

    #pragma unroll
    for (int it = 0; it < 2; ++it) {
        float4 acc = make_float4(0.f, 0.f, 0.f, 0.f);
        #pragma unroll 8
        for (int k = 0; k < R_REL; ++k) {
            float a = A[r * R_REL + k];
            float4 hv = *(const float4*)&h[k * RF_REL + c4];
            acc.x += a * hv.x; acc.y += a * hv.y;
            acc.z += a * hv.z; acc.w += a * hv.w;
        }
        __syncthreads();
        float4 hv = *(const float4*)&h[r * RF_REL + c4];
        hv.x = fmaxf(hv.x + acc.x * inv, 0.f);
        hv.y = fmaxf(hv.y + acc.y * inv, 0.f);
        hv.z = fmaxf(hv.z + acc.z * inv, 0.f);
        hv.w = fmaxf(hv.w + acc.w * inv, 0.f);
        *(float4*)&h[r * RF_REL + c4] = hv;
        __syncthreads();
    }

    for (int i = tid; i < RF_REL * DIM; i += 1024) A[i] = W_nn[i];
    __syncthreads();
    float4 acc = make_float4(b_nn[c4], b_nn[c4 + 1], b_nn[c4 + 2], b_nn[c4 + 3]);
    #pragma unroll 8
    for (int k = 0; k < RF_REL; ++k) {
        float hv = h[r * RF_REL + k];
        float4 wv = *(const float4*)&A[k * DIM + c4];
        acc.x += hv * wv.x; acc.y += hv * wv.y;
        acc.z += hv * wv.z; acc.w += hv * wv.w;
    }
    *(float4*)&g_wrel[r * DIM + c4] = acc;
}

// Tensor-core proj: x0h = fp16( x_in @ fc1 ), HMMA m16n8k16, fp32 accumulate.
// CTA = 128 nodes x 64 cols, K=128 staged once in fp16 smem (XOR-swizzled).
// 8 warps: 4 (M) x 2 (N); warp tile 32x32; 8 k-steps x 8 mma.
__global__ void proj_kernel(const float* __restrict__ x_in,
                            const float* __restrict__ fc1) {
    __shared__ __align__(16) unsigned As[128 * 64];  // fp16x2 [row][k2], swizzled, 32 KB
    __shared__ __align__(16) unsigned Bs[64 * 64];   // fp16x2 [n][k2],  swizzled, 16 KB
    int tid = threadIdx.x;  // 256
    int base = blockIdx.x * 128;

    // stage A: 128 rows x 32 float4, convert fp32->fp16x2, swizzle k2 by row
    for (int i = tid; i < 128 * 32; i += 256) {
        int r = i >> 5, c4 = i & 31;
        int n = base + r;
        float4 v = (n < N_NODES) ? *(const float4*)(x_in + (size_t)n * F_IN + c4 * 4)
                                 : make_float4(0.f, 0.f, 0.f, 0.f);
        __half2 h0 = __floats2half2_rn(v.x, v.y);
        __half2 h1 = __floats2half2_rn(v.z, v.w);
        int k2  = c4 * 2;
        int k2s = k2 ^ ((r & 7) << 2);
        *(uint2*)&As[r * 64 + k2s] = make_uint2(*(unsigned*)&h0, *(unsigned*)&h1);
    }
    // stage B: [n][k2] with pair = (fc1[2k2][n], fc1[2k2+1][n]), swizzled by n
    for (int i = tid; i < 64 * 64; i += 256) {
        int nn = i >> 6, k2 = i & 63;
        __half2 hh = __floats2half2_rn(fc1[(2 * k2) * DIM + nn],
                                       fc1[(2 * k2 + 1) * DIM + nn]);
        Bs[nn * 64 + (k2 ^ ((nn & 7) << 2))] = *(unsigned*)&hh;
    }
    __syncthreads();

    int w    = tid >> 5;
    int lane = tid & 31;
    int g = lane >> 2, c = lane & 3;
    int wm = w & 3, wn = w >> 2;
    int sw = g << 2;

    float acc[2][4][4];
    #pragma unroll
    for (int mt = 0; mt < 2; ++mt)
        #pragma unroll
        for (int nt = 0; nt < 4; ++nt)
            #pragma unroll
            for (int x = 0; x < 4; ++x) acc[mt][nt][x] = 0.f;

    #pragma unroll
    for (int ks = 0; ks < 8; ++ks) {
        int k2a = (8 * ks + c)     ^ sw;
        int k2b = (8 * ks + c + 4) ^ sw;
        unsigned a[2][4];
        #pragma unroll
        for (int mt = 0; mt < 2; ++mt) {
            int r0 = wm * 32 + mt * 16 + g;
            a[mt][0] = As[r0 * 64 + k2a];
            a[mt][1] = As[(r0 + 8) * 64 + k2a];
            a[mt][2] = As[r0 * 64 + k2b];
            a[mt][3] = As[(r0 + 8) * 64 + k2b];
        }
        unsigned b[4][2];
        #pragma unroll
        for (int nt = 0; nt < 4; ++nt) {
            int n0 = wn * 32 + nt * 8 + g;
            b[nt][0] = Bs[n0 * 64 + k2a];
            b[nt][1] = Bs[n0 * 64 + k2b];
        }
        #pragma unroll
        for (int mt = 0; mt < 2; ++mt)
            #pragma unroll
            for (int nt = 0; nt < 4; ++nt)
                mma16816(acc[mt][nt], a[mt], b[nt]);
    }

    // write fp16 mirror: rows g / g+8, cols 2c,2c+1 within each 16x8 tile
    #pragma unroll
    for (int mt = 0; mt < 2; ++mt) {
        int r0 = base + wm * 32 + mt * 16 + g;
        #pragma unroll
        for (int nt = 0; nt < 4; ++nt) {
            int col2 = wn * 16 + nt * 4 + c;   // fp16x2 column index (0..31)
            if (r0 < N_NODES)
                g_x0h[(size_t)r0 * 32 + col2] =
                    __floats2half2_rn(acc[mt][nt][0], acc[mt][nt][1]);
            if (r0 + 8 < N_NODES)
                g_x0h[(size_t)(r0 + 8) * 32 + col2] =
                    __floats2half2_rn(acc[mt][nt][2], acc[mt][nt][3]);
        }
    }
}

// Push edge sweep, 4-edge pipelined (R8-proven).
__global__ void edge_kernel(const int* __restrict__ dst,
                            int which_x, int count_deg) {
    __shared__ __align__(16) float ws[R_REL * DIM];  // 16 KB
    for (int i = threadIdx.x; i < R_REL * DIM; i += blockDim.x) ws[i] = g_wrel[i];
    __syncthreads();

    const __half2* __restrict__ xh = which_x ? g_x1h : g_x0h;

    int G    = (gridDim.x * blockDim.x) >> 4;
    int g    = (blockIdx.x * blockDim.x + threadIdx.x) >> 4;
    int lane = threadIdx.x & 15;
    const int NQUADS = N_EDGES / 4;

    for (int q = g; q < NQUADS; q += G) {
        int e = q * 4;
        uint4 pk = __ldg((const uint4*)(g_pk + e));   // broadcast within group
        uint4 dd = *(const uint4*)(dst + e);          // broadcast within group

        uint2 p0 = __ldg((const uint2*)(xh + (size_t)(pk.x >> 6) * 32 + lane * 2));
        uint2 p1 = __ldg((const uint2*)(xh + (size_t)(pk.y >> 6) * 32 + lane * 2));
        uint2 p2 = __ldg((const uint2*)(xh + (size_t)(pk.z >> 6) * 32 + lane * 2));
        uint2 p3 = __ldg((const uint2*)(xh + (size_t)(pk.w >> 6) * 32 + lane * 2));

        unsigned pks[4] = {pk.x, pk.y, pk.z, pk.w};
        unsigned dds[4] = {dd.x, dd.y, dd.z, dd.w};
        uint2    pps[4] = {p0, p1, p2, p3};
        #pragma unroll
        for (int j = 0; j < 4; ++j) {
            float2 f0 = __half22float2(*(__half2*)&pps[j].x);
            float2 f1 = __half22float2(*(__half2*)&pps[j].y);
            float4 wv = *(const float4*)&ws[(pks[j] & 63u) * DIM + lane * 4];
            red_add_v4(g_agg + (size_t)dds[j] * DIM + lane * 4,
                       f0.x * wv.x, f0.y * wv.y, f1.x * wv.z, f1.y * wv.w);
            if (count_deg && lane == 0) red_add_s32(&g_deg[dds[j]], 1);
        }
    }
}

// finish (layer 1 only): x1 = tanh(agg/deg + b1) -> fp16 mirror; re-zero agg.
__global__ void finish_kernel(const float* __restrict__ b) {
    int i = blockIdx.x * blockDim.x + threadIdx.x;
    if (i >= N_NODES * (DIM / 4)) return;
    int n = i >> 4, c4 = (i & 15) * 4;
    float4 v = ((const float4*)g_agg)[i];
    int d = g_deg[n];
    float inv = 1.0f / (float)(d > 0 ? d : 1);
    float4 bb = *(const float4*)(b + c4);
    v.x = tanhf(v.x * inv + bb.x);
    v.y = tanhf(v.y * inv + bb.y);
    v.z = tanhf(v.z * inv + bb.z);
    v.w = tanhf(v.w * inv + bb.w);
    __half2 h0 = __floats2half2_rn(v.x, v.y);
    __half2 h1 = __floats2half2_rn(v.z, v.w);
    uint2 p = make_uint2(*(uint32_t*)&h0, *(uint32_t*)&h1);
    *(uint2*)(g_x1h + (size_t)n * 32 + (c4 >> 1)) = p;
    ((float4*)g_agg)[i] = make_float4(0.f, 0.f, 0.f, 0.f);
}

// Fused finish2 + out:  out = tanh(agg/deg + b2) @ fc2_w + fc2_b.
__global__ void out_kernel(const float* __restrict__ b2,
                           const float* __restrict__ fc2w,
                           const float* __restrict__ fc2b,
                           float* __restrict__ out) {
    __shared__ float ws[DIM * NCLS];  // 4 KB
    __shared__ float xs[16 * DIM];    // 4 KB
    int tid = threadIdx.x;
    for (int i = tid; i < DIM * NCLS; i += 256) ws[i] = fc2w[i];

    int base = blockIdx.x * 16;
    {
        int nl = tid >> 4, c4 = (tid & 15) * 4;
        int n = base + nl;
        float4 v = *(const float4*)&g_agg[(size_t)n * DIM + c4];
        int d = g_deg[n];
        float inv = 1.0f / (float)(d > 0 ? d : 1);
        float4 bb = *(const float4*)(b2 + c4);
        v.x = tanhf(v.x * inv + bb.x);
        v.y = tanhf(v.y * inv + bb.y);
        v.z = tanhf(v.z * inv + bb.z);
        v.w = tanhf(v.w * inv + bb.w);
        *(float4*)&xs[nl * DIM + c4] = v;
    }
    __syncthreads();

    int nl = tid >> 4, k = tid & 15;
    float acc = fc2b[k];
    #pragma unroll
    for (int c = 0; c < DIM; ++c)
        acc += xs[nl * DIM + c] * ws[c * NCLS + k];
    out[(size_t)(base + nl) * NCLS + k] = acc;
}

// ---------------- launch ----------------
extern "C" void kernel_launch(void* const* d_in, const int* in_sizes, int n_in,
                              void* d_out, int out_size) {
    const float* x_in   = (const float*)d_in[0];
    const float* rel_x  = (const float*)d_in[1];
    const int*   ei     = (const int*)  d_in[2];
    const int*   et     = (const int*)  d_in[3];
    const int*   rel_ei = (const int*)  d_in[4];
    const float* rel_ea = (const float*)d_in[5];
    const float* fc1    = (const float*)d_in[6];
    const float* W_nn   = (const float*)d_in[7];
    const float* b_nn   = (const float*)d_in[8];
    const float* b1     = (const float*)d_in[9];
    const float* b2     = (const float*)d_in[10];
    const float* fc2w   = (const float*)d_in[11];
    const float* fc2b   = (const float*)d_in[12];
    float* out = (float*)d_out;

    // edge_kernel (conv1) kept as 4th launch -> profiled.
    init_kernel<<<(N_EDGES + 255) / 256, 256>>>(ei, et);              // 1
    rel_kernel<<<1, 1024>>>(rel_x, rel_ei, rel_ea, W_nn, b_nn);       // 2
    proj_kernel<<<(N_NODES + 127) / 128, 256>>>(x_in, fc1);           // 3

    edge_kernel<<<2048, 256>>>(ei + N_EDGES, 0, /*count_deg=*/1);     // 4 <- profiled
    finish_kernel<<<(N_NODES * 16 + 255) / 256, 256>>>(b1);           // 5

    edge_kernel<<<2048, 256>>>(ei + N_EDGES, 1, /*count_deg=*/0);     // 6
    out_kernel<<<N_NODES / 16, 256>>>(b2, fc2w, fc2b, out);           // 7
}

// round 13
// speedup vs baseline: 1.2420x; 1.0453x over previous
#include <cuda_runtime.h>
#include <cuda_fp16.h>
#include <cstdint>

#define N_NODES 100000
#define N_EDGES 2000000
#define DIM     64
#define F_IN    128
#define R_REL   64
#define ER_REL  2048
#define RF_REL  64
#define NCLS    16

// ---------------- scratch (static device memory; no allocations) ----------------
__device__ __align__(16) float g_agg[N_NODES * DIM];       // scatter accumulator
__device__ __align__(16) __half2 g_x0h[N_NODES * DIM / 2]; // fp16 mirror of x0 (proj out)
__device__ __align__(16) __half2 g_x1h[N_NODES * DIM / 2]; // fp16 mirror of x1 (conv1 out)
__device__ int g_deg[N_NODES];
__device__ __align__(16) float g_wrel[R_REL * DIM];        // per-relation edge weights
__device__ __align__(16) unsigned g_pk[N_EDGES];           // packed (src<<6)|etype

// ---------------- helpers ----------------
__device__ __forceinline__ void red_add_v4(float* addr, float a, float b, float c, float d) {
    asm volatile("red.global.add.v4.f32 [%0], {%1, %2, %3, %4};"
                 :: "l"(addr), "f"(a), "f"(b), "f"(c), "f"(d)
                 : "memory");
}
__device__ __forceinline__ void red_add_s32(int* addr, int v) {
    asm volatile("red.global.add.s32 [%0], %1;" :: "l"(addr), "r"(v) : "memory");
}
__device__ __forceinline__ void mma16816(float* d, const unsigned* a, const unsigned* b) {
    asm volatile("mma.sync.aligned.m16n8k16.row.col.f32.f16.f16.f32 "
                 "{%0,%1,%2,%3}, {%4,%5,%6,%7}, {%8,%9}, {%0,%1,%2,%3};"
                 : "+f"(d[0]), "+f"(d[1]), "+f"(d[2]), "+f"(d[3])
                 : "r"(a[0]), "r"(a[1]), "r"(a[2]), "r"(a[3]),
                   "r"(b[0]), "r"(b[1]));
}

// ---------------- init (split so proj is the 4th launch -> profiled) ----------
__global__ void pack_kernel(const int* __restrict__ src,
                            const int* __restrict__ et) {
    int i = blockIdx.x * blockDim.x + threadIdx.x;
    if (i < N_EDGES)
        g_pk[i] = ((unsigned)__ldg(src + i) << 6) | (unsigned)__ldg(et + i);
}

__global__ void zero_kernel() {
    int i = blockIdx.x * blockDim.x + threadIdx.x;
    if (i < N_NODES * DIM / 4)
        ((float4*)g_agg)[i] = make_float4(0.f, 0.f, 0.f, 0.f);
    if (i < N_NODES) g_deg[i] = 0;
}

// Relation conv x2 + w_rel = relu-chain(rel_x) @ W_nn + b_nn (GEMM form).
__global__ void rel_kernel(const float* __restrict__ rel_x,
                           const int*   __restrict__ rel_ei,
                           const float* __restrict__ rel_ea,
                           const float* __restrict__ W_nn,
                           const float* __restrict__ b_nn) {
    __shared__ __align__(16) float h[R_REL * RF_REL];
    __shared__ __align__(16) float A[R_REL * R_REL];
    __shared__ float cnt[R_REL];
    int tid = threadIdx.x;  // 1024

    for (int i = tid; i < R_REL * RF_REL; i += 1024) { h[i] = rel_x[i]; A[i] = 0.f; }
    if (tid < R_REL) cnt[tid] = 0.f;
    __syncthreads();

    for (int e = tid; e < ER_REL; e += 1024) {
        int sr = rel_ei[e];
        int dr = rel_ei[ER_REL + e];
        float a = rel_ea[e];
        atomicAdd(&A[dr * R_REL + sr], a);
        atomicAdd(&cnt[dr], 1.0f);
    }
    __syncthreads();

    int r  = tid >> 4;
    int c4 = (tid & 15) * 4;
    float inv = 1.0f / fmaxf(cnt[r], 1.0f);

    #pragma unroll
    for (int it = 0; it < 2; ++it) {
        float4 acc = make_float4(0.f, 0.f, 0.f, 0.f);
        #pragma unroll 8
        for (int k = 0; k < R_REL; ++k) {
            float a = A[r * R_REL + k];
            float4 hv = *(const float4*)&h[k * RF_REL + c4];
            acc.x += a * hv.x; acc.y += a * hv.y;
            acc.z += a * hv.z; acc.w += a * hv.w;
        }
        __syncthreads();
        float4 hv = *(const float4*)&h[r * RF_REL + c4];
        hv.x = fmaxf(hv.x + acc.x * inv, 0.f);
        hv.y = fmaxf(hv.y + acc.y * inv, 0.f);
        hv.z = fmaxf(hv.z + acc.z * inv, 0.f);
        hv.w = fmaxf(hv.w + acc.w * inv, 0.f);
        *(float4*)&h[r * RF_REL + c4] = hv;
        __syncthreads();
    }

    for (int i = tid; i < RF_REL * DIM; i += 1024) A[i] = W_nn[i];
    __syncthreads();
    float4 acc = make_float4(b_nn[c4], b_nn[c4 + 1], b_nn[c4 + 2], b_nn[c4 + 3]);
    #pragma unroll 8
    for (int k = 0; k < RF_REL; ++k) {
        float hv = h[r * RF_REL + k];
        float4 wv = *(const float4*)&A[k * DIM + c4];
        acc.x += hv * wv.x; acc.y += hv * wv.y;
        acc.z += hv * wv.z; acc.w += hv * wv.w;
    }
    *(float4*)&g_wrel[r * DIM + c4] = acc;
}

// Tensor-core proj: x0h = fp16( x_in @ fc1 ), HMMA m16n8k16, fp32 accumulate.
// CTA = 128 nodes x 64 cols, K=128 staged once in fp16 smem (XOR-swizzled).
// 8 warps: 4 (M) x 2 (N); warp tile 32x32; 8 k-steps x 8 mma.
__global__ void proj_kernel(const float* __restrict__ x_in,
                            const float* __restrict__ fc1) {
    __shared__ __align__(16) unsigned As[128 * 64];  // fp16x2 [row][k2], swizzled, 32 KB
    __shared__ __align__(16) unsigned Bs[64 * 64];   // fp16x2 [n][k2],  swizzled, 16 KB
    int tid = threadIdx.x;  // 256
    int base = blockIdx.x * 128;

    // stage A: 128 rows x 32 float4, convert fp32->fp16x2, swizzle k2 by row
    for (int i = tid; i < 128 * 32; i += 256) {
        int r = i >> 5, c4 = i & 31;
        int n = base + r;
        float4 v = (n < N_NODES) ? *(const float4*)(x_in + (size_t)n * F_IN + c4 * 4)
                                 : make_float4(0.f, 0.f, 0.f, 0.f);
        __half2 h0 = __floats2half2_rn(v.x, v.y);
        __half2 h1 = __floats2half2_rn(v.z, v.w);
        int k2  = c4 * 2;
        int k2s = k2 ^ ((r & 7) << 2);
        *(uint2*)&As[r * 64 + k2s] = make_uint2(*(unsigned*)&h0, *(unsigned*)&h1);
    }
    // stage B: coalesced — consecutive threads walk nn along an fc1 row.
    // Bs[nn][k2] = (fc1[2k2][nn], fc1[2k2+1][nn]), swizzled by nn.
    for (int i = tid; i < 64 * 64; i += 256) {
        int k2 = i >> 6, nn = i & 63;
        __half2 hh = __floats2half2_rn(fc1[(2 * k2) * DIM + nn],
                                       fc1[(2 * k2 + 1) * DIM + nn]);
        Bs[nn * 64 + (k2 ^ ((nn & 7) << 2))] = *(unsigned*)&hh;
    }
    __syncthreads();

    int w    = tid >> 5;
    int lane = tid & 31;
    int g = lane >> 2, c = lane & 3;
    int wm = w & 3, wn = w >> 2;
    int sw = g << 2;

    float acc[2][4][4];
    #pragma unroll
    for (int mt = 0; mt < 2; ++mt)
        #pragma unroll
        for (int nt = 0; nt < 4; ++nt)
            #pragma unroll
            for (int x = 0; x < 4; ++x) acc[mt][nt][x] = 0.f;

    #pragma unroll
    for (int ks = 0; ks < 8; ++ks) {
        int k2a = (8 * ks + c)     ^ sw;
        int k2b = (8 * ks + c + 4) ^ sw;
        unsigned a[2][4];
        #pragma unroll
        for (int mt = 0; mt < 2; ++mt) {
            int r0 = wm * 32 + mt * 16 + g;
            a[mt][0] = As[r0 * 64 + k2a];
            a[mt][1] = As[(r0 + 8) * 64 + k2a];
            a[mt][2] = As[r0 * 64 + k2b];
            a[mt][3] = As[(r0 + 8) * 64 + k2b];
        }
        unsigned b[4][2];
        #pragma unroll
        for (int nt = 0; nt < 4; ++nt) {
            int n0 = wn * 32 + nt * 8 + g;
            b[nt][0] = Bs[n0 * 64 + k2a];
            b[nt][1] = Bs[n0 * 64 + k2b];
        }
        #pragma unroll
        for (int mt = 0; mt < 2; ++mt)
            #pragma unroll
            for (int nt = 0; nt < 4; ++nt)
                mma16816(acc[mt][nt], a[mt], b[nt]);
    }

    // write fp16 mirror: rows g / g+8, cols 2c,2c+1 within each 16x8 tile
    #pragma unroll
    for (int mt = 0; mt < 2; ++mt) {
        int r0 = base + wm * 32 + mt * 16 + g;
        #pragma unroll
        for (int nt = 0; nt < 4; ++nt) {
            int col2 = wn * 16 + nt * 4 + c;   // fp16x2 column index (0..31)
            if (r0 < N_NODES)
                g_x0h[(size_t)r0 * 32 + col2] =
                    __floats2half2_rn(acc[mt][nt][0], acc[mt][nt][1]);
            if (r0 + 8 < N_NODES)
                g_x0h[(size_t)(r0 + 8) * 32 + col2] =
                    __floats2half2_rn(acc[mt][nt][2], acc[mt][nt][3]);
        }
    }
}

// Push edge sweep, 4-edge pipelined (R8-proven).
__global__ void edge_kernel(const int* __restrict__ dst,
                            int which_x, int count_deg) {
    __shared__ __align__(16) float ws[R_REL * DIM];  // 16 KB
    for (int i = threadIdx.x; i < R_REL * DIM; i += blockDim.x) ws[i] = g_wrel[i];
    __syncthreads();

    const __half2* __restrict__ xh = which_x ? g_x1h : g_x0h;

    int G    = (gridDim.x * blockDim.x) >> 4;
    int g    = (blockIdx.x * blockDim.x + threadIdx.x) >> 4;
    int lane = threadIdx.x & 15;
    const int NQUADS = N_EDGES / 4;

    for (int q = g; q < NQUADS; q += G) {
        int e = q * 4;
        uint4 pk = __ldg((const uint4*)(g_pk + e));   // broadcast within group
        uint4 dd = *(const uint4*)(dst + e);          // broadcast within group

        uint2 p0 = __ldg((const uint2*)(xh + (size_t)(pk.x >> 6) * 32 + lane * 2));
        uint2 p1 = __ldg((const uint2*)(xh + (size_t)(pk.y >> 6) * 32 + lane * 2));
        uint2 p2 = __ldg((const uint2*)(xh + (size_t)(pk.z >> 6) * 32 + lane * 2));
        uint2 p3 = __ldg((const uint2*)(xh + (size_t)(pk.w >> 6) * 32 + lane * 2));

        unsigned pks[4] = {pk.x, pk.y, pk.z, pk.w};
        unsigned dds[4] = {dd.x, dd.y, dd.z, dd.w};
        uint2    pps[4] = {p0, p1, p2, p3};
        #pragma unroll
        for (int j = 0; j < 4; ++j) {
            float2 f0 = __half22float2(*(__half2*)&pps[j].x);
            float2 f1 = __half22float2(*(__half2*)&pps[j].y);
            float4 wv = *(const float4*)&ws[(pks[j] & 63u) * DIM + lane * 4];
            red_add_v4(g_agg + (size_t)dds[j] * DIM + lane * 4,
                       f0.x * wv.x, f0.y * wv.y, f1.x * wv.z, f1.y * wv.w);
            if (count_deg && lane == 0) red_add_s32(&g_deg[dds[j]], 1);
        }
    }
}

// finish (layer 1 only): x1 = tanh(agg/deg + b1) -> fp16 mirror; re-zero agg.
__global__ void finish_kernel(const float* __restrict__ b) {
    int i = blockIdx.x * blockDim.x + threadIdx.x;
    if (i >= N_NODES * (DIM / 4)) return;
    int n = i >> 4, c4 = (i & 15) * 4;
    float4 v = ((const float4*)g_agg)[i];
    int d = g_deg[n];
    float inv = 1.0f / (float)(d > 0 ? d : 1);
    float4 bb = *(const float4*)(b + c4);
    v.x = tanhf(v.x * inv + bb.x);
    v.y = tanhf(v.y * inv + bb.y);
    v.z = tanhf(v.z * inv + bb.z);
    v.w = tanhf(v.w * inv + bb.w);
    __half2 h0 = __floats2half2_rn(v.x, v.y);
    __half2 h1 = __floats2half2_rn(v.z, v.w);
    uint2 p = make_uint2(*(uint32_t*)&h0, *(uint32_t*)&h1);
    *(uint2*)(g_x1h + (size_t)n * 32 + (c4 >> 1)) = p;
    ((float4*)g_agg)[i] = make_float4(0.f, 0.f, 0.f, 0.f);
}

// Fused finish2 + out:  out = tanh(agg/deg + b2) @ fc2_w + fc2_b.
__global__ void out_kernel(const float* __restrict__ b2,
                           const float* __restrict__ fc2w,
                           const float* __restrict__ fc2b,
                           float* __restrict__ out) {
    __shared__ float ws[DIM * NCLS];  // 4 KB
    __shared__ float xs[16 * DIM];    // 4 KB
    int tid = threadIdx.x;
    for (int i = tid; i < DIM * NCLS; i += 256) ws[i] = fc2w[i];

    int base = blockIdx.x * 16;
    {
        int nl = tid >> 4, c4 = (tid & 15) * 4;
        int n = base + nl;
        float4 v = *(const float4*)&g_agg[(size_t)n * DIM + c4];
        int d = g_deg[n];
        float inv = 1.0f / (float)(d > 0 ? d : 1);
        float4 bb = *(const float4*)(b2 + c4);
        v.x = tanhf(v.x * inv + bb.x);
        v.y = tanhf(v.y * inv + bb.y);
        v.z = tanhf(v.z * inv + bb.z);
        v.w = tanhf(v.w * inv + bb.w);
        *(float4*)&xs[nl * DIM + c4] = v;
    }
    __syncthreads();

    int nl = tid >> 4, k = tid & 15;
    float acc = fc2b[k];
    #pragma unroll
    for (int c = 0; c < DIM; ++c)
        acc += xs[nl * DIM + c] * ws[c * NCLS + k];
    out[(size_t)(base + nl) * NCLS + k] = acc;
}

// ---------------- launch ----------------
extern "C" void kernel_launch(void* const* d_in, const int* in_sizes, int n_in,
                              void* d_out, int out_size) {
    const float* x_in   = (const float*)d_in[0];
    const float* rel_x  = (const float*)d_in[1];
    const int*   ei     = (const int*)  d_in[2];
    const int*   et     = (const int*)  d_in[3];
    const int*   rel_ei = (const int*)  d_in[4];
    const float* rel_ea = (const float*)d_in[5];
    const float* fc1    = (const float*)d_in[6];
    const float* W_nn   = (const float*)d_in[7];
    const float* b_nn   = (const float*)d_in[8];
    const float* b1     = (const float*)d_in[9];
    const float* b2     = (const float*)d_in[10];
    const float* fc2w   = (const float*)d_in[11];
    const float* fc2b   = (const float*)d_in[12];
    float* out = (float*)d_out;

    // proj_kernel is the 4th launch -> profiled this round.
    pack_kernel<<<(N_EDGES + 255) / 256, 256>>>(ei, et);              // 1
    zero_kernel<<<(N_NODES * DIM / 4 + 255) / 256, 256>>>();          // 2
    rel_kernel<<<1, 1024>>>(rel_x, rel_ei, rel_ea, W_nn, b_nn);       // 3
    proj_kernel<<<(N_NODES + 127) / 128, 256>>>(x_in, fc1);           // 4 <- profiled

    edge_kernel<<<2048, 256>>>(ei + N_EDGES, 0, /*count_deg=*/1);     // 5
    finish_kernel<<<(N_NODES * 16 + 255) / 256, 256>>>(b1);           // 6

    edge_kernel<<<2048, 256>>>(ei + N_EDGES, 1, /*count_deg=*/0);     // 7
    out_kernel<<<N_NODES / 16, 256>>>(b2, fc2w, fc2b, out);           // 8
}

// round 14
// speedup vs baseline: 1.3013x; 1.0478x over previous
#include <cuda_runtime.h>
#include <cuda_fp16.h>
#include <cstdint>

#define N_NODES 100000
#define N_EDGES 2000000
#define DIM     64
#define F_IN    128
#define R_REL   64
#define ER_REL  2048
#define RF_REL  64
#define NCLS    16

// ---------------- scratch (static device memory; no allocations) ----------------
__device__ __align__(16) float g_agg[N_NODES * DIM];       // scatter accumulator
__device__ __align__(16) __half2 g_x0h[N_NODES * DIM / 2]; // fp16 mirror of x0 (proj out)
__device__ __align__(16) __half2 g_x1h[N_NODES * DIM / 2]; // fp16 mirror of x1 (conv1 out)
__device__ int g_deg[N_NODES];
__device__ __align__(16) float g_wrel[R_REL * DIM];        // per-relation edge weights
__device__ __align__(16) unsigned g_pk[N_EDGES];           // packed (src<<6)|etype

// ---------------- helpers ----------------
__device__ __forceinline__ void red_add_v4(float* addr, float a, float b, float c, float d) {
    asm volatile("red.global.add.v4.f32 [%0], {%1, %2, %3, %4};"
                 :: "l"(addr), "f"(a), "f"(b), "f"(c), "f"(d)
                 : "memory");
}
__device__ __forceinline__ void red_add_s32(int* addr, int v) {
    asm volatile("red.global.add.s32 [%0], %1;" :: "l"(addr), "r"(v) : "memory");
}
__device__ __forceinline__ void mma16816(float* d, const unsigned* a, const unsigned* b) {
    asm volatile("mma.sync.aligned.m16n8k16.row.col.f32.f16.f16.f32 "
                 "{%0,%1,%2,%3}, {%4,%5,%6,%7}, {%8,%9}, {%0,%1,%2,%3};"
                 : "+f"(d[0]), "+f"(d[1]), "+f"(d[2]), "+f"(d[3])
                 : "r"(a[0]), "r"(a[1]), "r"(a[2]), "r"(a[3]),
                   "r"(b[0]), "r"(b[1]));
}

// ---------------- init ----------------
__global__ void pack_kernel(const int* __restrict__ src,
                            const int* __restrict__ et) {
    int i = blockIdx.x * blockDim.x + threadIdx.x;
    if (i < N_EDGES)
        g_pk[i] = ((unsigned)__ldg(src + i) << 6) | (unsigned)__ldg(et + i);
}

__global__ void zero_kernel() {
    int i = blockIdx.x * blockDim.x + threadIdx.x;
    if (i < N_NODES * DIM / 4)
        ((float4*)g_agg)[i] = make_float4(0.f, 0.f, 0.f, 0.f);
    if (i < N_NODES) g_deg[i] = 0;
}

// Relation conv x2 + w_rel = relu-chain(rel_x) @ W_nn + b_nn (GEMM form).
__global__ void rel_kernel(const float* __restrict__ rel_x,
                           const int*   __restrict__ rel_ei,
                           const float* __restrict__ rel_ea,
                           const float* __restrict__ W_nn,
                           const float* __restrict__ b_nn) {
    __shared__ __align__(16) float h[R_REL * RF_REL];
    __shared__ __align__(16) float A[R_REL * R_REL];
    __shared__ float cnt[R_REL];
    int tid = threadIdx.x;  // 1024

    for (int i = tid; i < R_REL * RF_REL; i += 1024) { h[i] = rel_x[i]; A[i] = 0.f; }
    if (tid < R_REL) cnt[tid] = 0.f;
    __syncthreads();

    for (int e = tid; e < ER_REL; e += 1024) {
        int sr = rel_ei[e];
        int dr = rel_ei[ER_REL + e];
        float a = rel_ea[e];
        atomicAdd(&A[dr * R_REL + sr], a);
        atomicAdd(&cnt[dr], 1.0f);
    }
    __syncthreads();

    int r  = tid >> 4;
    int c4 = (tid & 15) * 4;
    float inv = 1.0f / fmaxf(cnt[r], 1.0f);

    #pragma unroll
    for (int it = 0; it < 2; ++it) {
        float4 acc = make_float4(0.f, 0.f, 0.f, 0.f);
        #pragma unroll 8
        for (int k = 0; k < R_REL; ++k) {
            float a = A[r * R_REL + k];
            float4 hv = *(const float4*)&h[k * RF_REL + c4];
            acc.x += a * hv.x; acc.y += a * hv.y;
            acc.z += a * hv.z; acc.w += a * hv.w;
        }
        __syncthreads();
        float4 hv = *(const float4*)&h[r * RF_REL + c4];
        hv.x = fmaxf(hv.x + acc.x * inv, 0.f);
        hv.y = fmaxf(hv.y + acc.y * inv, 0.f);
        hv.z = fmaxf(hv.z + acc.z * inv, 0.f);
        hv.w = fmaxf(hv.w + acc.w * inv, 0.f);
        *(float4*)&h[r * RF_REL + c4] = hv;
        __syncthreads();
    }

    for (int i = tid; i < RF_REL * DIM; i += 1024) A[i] = W_nn[i];
    __syncthreads();
    float4 acc = make_float4(b_nn[c4], b_nn[c4 + 1], b_nn[c4 + 2], b_nn[c4 + 3]);
    #pragma unroll 8
    for (int k = 0; k < RF_REL; ++k) {
        float hv = h[r * RF_REL + k];
        float4 wv = *(const float4*)&A[k * DIM + c4];
        acc.x += hv * wv.x; acc.y += hv * wv.y;
        acc.z += hv * wv.z; acc.w += hv * wv.w;
    }
    *(float4*)&g_wrel[r * DIM + c4] = acc;
}

// Tensor-core proj, 64-node CTA (32 KB smem -> ~6 CTAs/SM for latency hiding).
// 8 warps = 2 (M, 32 rows each) x 4 (N, 16 cols each); warp tile 32x16;
// HMMA m16n8k16, fp32 accumulate. Swizzle identical to R13 (r&7 == g).
__global__ void __launch_bounds__(256)
proj_kernel(const float* __restrict__ x_in,
            const float* __restrict__ fc1) {
    __shared__ __align__(16) unsigned As[64 * 64];   // fp16x2 [row][k2], swizzled, 16 KB
    __shared__ __align__(16) unsigned Bs[64 * 64];   // fp16x2 [n][k2],  swizzled, 16 KB
    int tid = threadIdx.x;  // 256
    int base = blockIdx.x * 64;

    // stage A: 64 rows x 32 float4 (8 independent loads per thread)
    #pragma unroll
    for (int it = 0; it < 8; ++it) {
        int i = tid + it * 256;
        int r = i >> 5, c4 = i & 31;
        int n = base + r;
        float4 v = (n < N_NODES) ? *(const float4*)(x_in + (size_t)n * F_IN + c4 * 4)
                                 : make_float4(0.f, 0.f, 0.f, 0.f);
        __half2 h0 = __floats2half2_rn(v.x, v.y);
        __half2 h1 = __floats2half2_rn(v.z, v.w);
        int k2  = c4 * 2;
        int k2s = k2 ^ ((r & 7) << 2);
        *(uint2*)&As[r * 64 + k2s] = make_uint2(*(unsigned*)&h0, *(unsigned*)&h1);
    }
    // stage B: coalesced over nn. Bs[nn][k2] = (fc1[2k2][nn], fc1[2k2+1][nn])
    #pragma unroll
    for (int it = 0; it < 16; ++it) {
        int i = tid + it * 256;
        int k2 = i >> 6, nn = i & 63;
        __half2 hh = __floats2half2_rn(fc1[(2 * k2) * DIM + nn],
                                       fc1[(2 * k2 + 1) * DIM + nn]);
        Bs[nn * 64 + (k2 ^ ((nn & 7) << 2))] = *(unsigned*)&hh;
    }
    __syncthreads();

    int w    = tid >> 5;
    int lane = tid & 31;
    int g = lane >> 2, c = lane & 3;
    int wm = w & 1, wn = w >> 1;       // 2 (M) x 4 (N)
    int sw = g << 2;

    float acc[2][2][4];
    #pragma unroll
    for (int mt = 0; mt < 2; ++mt)
        #pragma unroll
        for (int nt = 0; nt < 2; ++nt)
            #pragma unroll
            for (int x = 0; x < 4; ++x) acc[mt][nt][x] = 0.f;

    #pragma unroll
    for (int ks = 0; ks < 8; ++ks) {
        int k2a = (8 * ks + c)     ^ sw;
        int k2b = (8 * ks + c + 4) ^ sw;
        unsigned a[2][4];
        #pragma unroll
        for (int mt = 0; mt < 2; ++mt) {
            int r0 = wm * 32 + mt * 16 + g;
            a[mt][0] = As[r0 * 64 + k2a];
            a[mt][1] = As[(r0 + 8) * 64 + k2a];
            a[mt][2] = As[r0 * 64 + k2b];
            a[mt][3] = As[(r0 + 8) * 64 + k2b];
        }
        unsigned b[2][2];
        #pragma unroll
        for (int nt = 0; nt < 2; ++nt) {
            int n0 = wn * 16 + nt * 8 + g;
            b[nt][0] = Bs[n0 * 64 + k2a];
            b[nt][1] = Bs[n0 * 64 + k2b];
        }
        #pragma unroll
        for (int mt = 0; mt < 2; ++mt)
            #pragma unroll
            for (int nt = 0; nt < 2; ++nt)
                mma16816(acc[mt][nt], a[mt], b[nt]);
    }

    // write fp16 mirror: rows g / g+8, cols 2c,2c+1 within each 16x8 tile
    #pragma unroll
    for (int mt = 0; mt < 2; ++mt) {
        int r0 = base + wm * 32 + mt * 16 + g;
        #pragma unroll
        for (int nt = 0; nt < 2; ++nt) {
            int col2 = wn * 8 + nt * 4 + c;    // fp16x2 column index (0..31)
            if (r0 < N_NODES)
                g_x0h[(size_t)r0 * 32 + col2] =
                    __floats2half2_rn(acc[mt][nt][0], acc[mt][nt][1]);
            if (r0 + 8 < N_NODES)
                g_x0h[(size_t)(r0 + 8) * 32 + col2] =
                    __floats2half2_rn(acc[mt][nt][2], acc[mt][nt][3]);
        }
    }
}

// Push edge sweep, 4-edge pipelined (R8-proven).
__global__ void edge_kernel(const int* __restrict__ dst,
                            int which_x, int count_deg) {
    __shared__ __align__(16) float ws[R_REL * DIM];  // 16 KB
    for (int i = threadIdx.x; i < R_REL * DIM; i += blockDim.x) ws[i] = g_wrel[i];
    __syncthreads();

    const __half2* __restrict__ xh = which_x ? g_x1h : g_x0h;

    int G    = (gridDim.x * blockDim.x) >> 4;
    int g    = (blockIdx.x * blockDim.x + threadIdx.x) >> 4;
    int lane = threadIdx.x & 15;
    const int NQUADS = N_EDGES / 4;

    for (int q = g; q < NQUADS; q += G) {
        int e = q * 4;
        uint4 pk = __ldg((const uint4*)(g_pk + e));   // broadcast within group
        uint4 dd = *(const uint4*)(dst + e);          // broadcast within group

        uint2 p0 = __ldg((const uint2*)(xh + (size_t)(pk.x >> 6) * 32 + lane * 2));
        uint2 p1 = __ldg((const uint2*)(xh + (size_t)(pk.y >> 6) * 32 + lane * 2));
        uint2 p2 = __ldg((const uint2*)(xh + (size_t)(pk.z >> 6) * 32 + lane * 2));
        uint2 p3 = __ldg((const uint2*)(xh + (size_t)(pk.w >> 6) * 32 + lane * 2));

        unsigned pks[4] = {pk.x, pk.y, pk.z, pk.w};
        unsigned dds[4] = {dd.x, dd.y, dd.z, dd.w};
        uint2    pps[4] = {p0, p1, p2, p3};
        #pragma unroll
        for (int j = 0; j < 4; ++j) {
            float2 f0 = __half22float2(*(__half2*)&pps[j].x);
            float2 f1 = __half22float2(*(__half2*)&pps[j].y);
            float4 wv = *(const float4*)&ws[(pks[j] & 63u) * DIM + lane * 4];
            red_add_v4(g_agg + (size_t)dds[j] * DIM + lane * 4,
                       f0.x * wv.x, f0.y * wv.y, f1.x * wv.z, f1.y * wv.w);
            if (count_deg && lane == 0) red_add_s32(&g_deg[dds[j]], 1);
        }
    }
}

// finish (layer 1 only): x1 = tanh(agg/deg + b1) -> fp16 mirror; re-zero agg.
__global__ void finish_kernel(const float* __restrict__ b) {
    int i = blockIdx.x * blockDim.x + threadIdx.x;
    if (i >= N_NODES * (DIM / 4)) return;
    int n = i >> 4, c4 = (i & 15) * 4;
    float4 v = ((const float4*)g_agg)[i];
    int d = g_deg[n];
    float inv = 1.0f / (float)(d > 0 ? d : 1);
    float4 bb = *(const float4*)(b + c4);
    v.x = tanhf(v.x * inv + bb.x);
    v.y = tanhf(v.y * inv + bb.y);
    v.z = tanhf(v.z * inv + bb.z);
    v.w = tanhf(v.w * inv + bb.w);
    __half2 h0 = __floats2half2_rn(v.x, v.y);
    __half2 h1 = __floats2half2_rn(v.z, v.w);
    uint2 p = make_uint2(*(uint32_t*)&h0, *(uint32_t*)&h1);
    *(uint2*)(g_x1h + (size_t)n * 32 + (c4 >> 1)) = p;
    ((float4*)g_agg)[i] = make_float4(0.f, 0.f, 0.f, 0.f);
}

// Fused finish2 + out:  out = tanh(agg/deg + b2) @ fc2_w + fc2_b.
__global__ void out_kernel(const float* __restrict__ b2,
                           const float* __restrict__ fc2w,
                           const float* __restrict__ fc2b,
                           float* __restrict__ out) {
    __shared__ float ws[DIM * NCLS];  // 4 KB
    __shared__ float xs[16 * DIM];    // 4 KB
    int tid = threadIdx.x;
    for (int i = tid; i < DIM * NCLS; i += 256) ws[i] = fc2w[i];

    int base = blockIdx.x * 16;
    {
        int nl = tid >> 4, c4 = (tid & 15) * 4;
        int n = base + nl;
        float4 v = *(const float4*)&g_agg[(size_t)n * DIM + c4];
        int d = g_deg[n];
        float inv = 1.0f / (float)(d > 0 ? d : 1);
        float4 bb = *(const float4*)(b2 + c4);
        v.x = tanhf(v.x * inv + bb.x);
        v.y = tanhf(v.y * inv + bb.y);
        v.z = tanhf(v.z * inv + bb.z);
        v.w = tanhf(v.w * inv + bb.w);
        *(float4*)&xs[nl * DIM + c4] = v;
    }
    __syncthreads();

    int nl = tid >> 4, k = tid & 15;
    float acc = fc2b[k];
    #pragma unroll
    for (int c = 0; c < DIM; ++c)
        acc += xs[nl * DIM + c] * ws[c * NCLS + k];
    out[(size_t)(base + nl) * NCLS + k] = acc;
}

// ---------------- launch ----------------
extern "C" void kernel_launch(void* const* d_in, const int* in_sizes, int n_in,
                              void* d_out, int out_size) {
    const float* x_in   = (const float*)d_in[0];
    const float* rel_x  = (const float*)d_in[1];
    const int*   ei     = (const int*)  d_in[2];
    const int*   et     = (const int*)  d_in[3];
    const int*   rel_ei = (const int*)  d_in[4];
    const float* rel_ea = (const float*)d_in[5];
    const float* fc1    = (const float*)d_in[6];
    const float* W_nn   = (const float*)d_in[7];
    const float* b_nn   = (const float*)d_in[8];
    const float* b1     = (const float*)d_in[9];
    const float* b2     = (const float*)d_in[10];
    const float* fc2w   = (const float*)d_in[11];
    const float* fc2b   = (const float*)d_in[12];
    float* out = (float*)d_out;

    // proj_kernel is the 4th launch -> profiled this round.
    pack_kernel<<<(N_EDGES + 255) / 256, 256>>>(ei, et);              // 1
    zero_kernel<<<(N_NODES * DIM / 4 + 255) / 256, 256>>>();          // 2
    rel_kernel<<<1, 1024>>>(rel_x, rel_ei, rel_ea, W_nn, b_nn);       // 3
    proj_kernel<<<(N_NODES + 63) / 64, 256>>>(x_in, fc1);             // 4 <- profiled

    edge_kernel<<<2048, 256>>>(ei + N_EDGES, 0, /*count_deg=*/1);     // 5
    finish_kernel<<<(N_NODES * 16 + 255) / 256, 256>>>(b1);           // 6

    edge_kernel<<<2048, 256>>>(ei + N_EDGES, 1, /*count_deg=*/0);     // 7
    out_kernel<<<N_NODES / 16, 256>>>(b2, fc2w, fc2b, out);           // 8
}

// round 15
// speedup vs baseline: 1.3240x; 1.0174x over previous
#include <cuda_runtime.h>
#include <cuda_fp16.h>
#include <cstdint>

#define N_NODES 100000
#define N_EDGES 2000000
#define DIM     64
#define F_IN    128
#define R_REL   64
#define ER_REL  2048
#define RF_REL  64
#define NCLS    16

// ---------------- scratch (static device memory; no allocations) ----------------
__device__ __align__(16) float g_agg[N_NODES * DIM];       // scatter accumulator
__device__ __align__(16) __half2 g_x0h[N_NODES * DIM / 2]; // fp16 mirror of x0 (proj out)
__device__ __align__(16) __half2 g_x1h[N_NODES * DIM / 2]; // fp16 mirror of x1 (conv1 out)
__device__ int g_deg[N_NODES];
__device__ __align__(16) float g_wrel[R_REL * DIM];        // per-relation edge weights
__device__ __align__(16) unsigned g_pk[N_EDGES];           // packed (src<<6)|etype
__device__ __align__(16) unsigned g_Bsw[64 * 64];          // fc1 as fp16x2, transposed + swizzled

// ---------------- helpers ----------------
__device__ __forceinline__ void red_add_v4(float* addr, float a, float b, float c, float d) {
    asm volatile("red.global.add.v4.f32 [%0], {%1, %2, %3, %4};"
                 :: "l"(addr), "f"(a), "f"(b), "f"(c), "f"(d)
                 : "memory");
}
__device__ __forceinline__ void red_add_s32(int* addr, int v) {
    asm volatile("red.global.add.s32 [%0], %1;" :: "l"(addr), "r"(v) : "memory");
}
__device__ __forceinline__ void mma16816(float* d, const unsigned* a, const unsigned* b) {
    asm volatile("mma.sync.aligned.m16n8k16.row.col.f32.f16.f16.f32 "
                 "{%0,%1,%2,%3}, {%4,%5,%6,%7}, {%8,%9}, {%0,%1,%2,%3};"
                 : "+f"(d[0]), "+f"(d[1]), "+f"(d[2]), "+f"(d[3])
                 : "r"(a[0]), "r"(a[1]), "r"(a[2]), "r"(a[3]),
                   "r"(b[0]), "r"(b[1]));
}

// ---------------- fused init: pack edges + zero agg + zero deg ----------------
__global__ void init_kernel(const int* __restrict__ src,
                            const int* __restrict__ et) {
    int i = blockIdx.x * blockDim.x + threadIdx.x;
    if (i < N_EDGES)
        g_pk[i] = ((unsigned)__ldg(src + i) << 6) | (unsigned)__ldg(et + i);
    if (i < N_NODES * DIM / 4)
        ((float4*)g_agg)[i] = make_float4(0.f, 0.f, 0.f, 0.f);
    if (i < N_NODES) g_deg[i] = 0;
}

// One-shot: fc1 [128,64] fp32 -> fp16x2 k-pairs, transposed to [n][k2], swizzled.
// g_Bsw[nn*64 + (k2 ^ ((nn&7)<<2))] = (fc1[2k2][nn], fc1[2k2+1][nn])
__global__ void prep_b_kernel(const float* __restrict__ fc1) {
    int i = blockIdx.x * blockDim.x + threadIdx.x;   // 4096 threads
    int k2 = i >> 6, nn = i & 63;                    // coalesced over nn
    __half2 hh = __floats2half2_rn(fc1[(2 * k2) * DIM + nn],
                                   fc1[(2 * k2 + 1) * DIM + nn]);
    g_Bsw[nn * 64 + (k2 ^ ((nn & 7) << 2))] = *(unsigned*)&hh;
}

// Relation conv x2 + w_rel = relu-chain(rel_x) @ W_nn + b_nn (GEMM form).
__global__ void rel_kernel(const float* __restrict__ rel_x,
                           const int*   __restrict__ rel_ei,
                           const float* __restrict__ rel_ea,
                           const float* __restrict__ W_nn,
                           const float* __restrict__ b_nn) {
    __shared__ __align__(16) float h[R_REL * RF_REL];
    __shared__ __align__(16) float A[R_REL * R_REL];
    __shared__ float cnt[R_REL];
    int tid = threadIdx.x;  // 1024

    for (int i = tid; i < R_REL * RF_REL; i += 1024) { h[i] = rel_x[i]; A[i] = 0.f; }
    if (tid < R_REL) cnt[tid] = 0.f;
    __syncthreads();

    for (int e = tid; e < ER_REL; e += 1024) {
        int sr = rel_ei[e];
        int dr = rel_ei[ER_REL + e];
        float a = rel_ea[e];
        atomicAdd(&A[dr * R_REL + sr], a);
        atomicAdd(&cnt[dr], 1.0f);
    }
    __syncthreads();

    int r  = tid >> 4;
    int c4 = (tid & 15) * 4;
    float inv = 1.0f / fmaxf(cnt[r], 1.0f);

    #pragma unroll
    for (int it = 0; it < 2; ++it) {
        float4 acc = make_float4(0.f, 0.f, 0.f, 0.f);
        #pragma unroll 8
        for (int k = 0; k < R_REL; ++k) {
            float a = A[r * R_REL + k];
            float4 hv = *(const float4*)&h[k * RF_REL + c4];
            acc.x += a * hv.x; acc.y += a * hv.y;
            acc.z += a * hv.z; acc.w += a * hv.w;
        }
        __syncthreads();
        float4 hv = *(const float4*)&h[r * RF_REL + c4];
        hv.x = fmaxf(hv.x + acc.x * inv, 0.f);
        hv.y = fmaxf(hv.y + acc.y * inv, 0.f);
        hv.z = fmaxf(hv.z + acc.z * inv, 0.f);
        hv.w = fmaxf(hv.w + acc.w * inv, 0.f);
        *(float4*)&h[r * RF_REL + c4] = hv;
        __syncthreads();
    }

    for (int i = tid; i < RF_REL * DIM; i += 1024) A[i] = W_nn[i];
    __syncthreads();
    float4 acc = make_float4(b_nn[c4], b_nn[c4 + 1], b_nn[c4 + 2], b_nn[c4 + 3]);
    #pragma unroll 8
    for (int k = 0; k < RF_REL; ++k) {
        float hv = h[r * RF_REL + k];
        float4 wv = *(const float4*)&A[k * DIM + c4];
        acc.x += hv * wv.x; acc.y += hv * wv.y;
        acc.z += hv * wv.z; acc.w += hv * wv.w;
    }
    *(float4*)&g_wrel[r * DIM + c4] = acc;
}

// Tensor-core proj, 64-node CTA; B tile copied pre-swizzled from g_Bsw.
// 8 warps = 2 (M) x 4 (N); warp tile 32x16; HMMA m16n8k16, fp32 accumulate.
__global__ void __launch_bounds__(256)
proj_kernel(const float* __restrict__ x_in) {
    __shared__ __align__(16) unsigned As[64 * 64];   // fp16x2 [row][k2], swizzled, 16 KB
    __shared__ __align__(16) unsigned Bs[64 * 64];   // fp16x2 [n][k2],  swizzled, 16 KB
    int tid = threadIdx.x;  // 256
    int base = blockIdx.x * 64;

    // stage A: 64 rows x 32 float4 (8 independent loads per thread)
    #pragma unroll
    for (int it = 0; it < 8; ++it) {
        int i = tid + it * 256;
        int r = i >> 5, c4 = i & 31;
        int n = base + r;
        float4 v = (n < N_NODES) ? *(const float4*)(x_in + (size_t)n * F_IN + c4 * 4)
                                 : make_float4(0.f, 0.f, 0.f, 0.f);
        __half2 h0 = __floats2half2_rn(v.x, v.y);
        __half2 h1 = __floats2half2_rn(v.z, v.w);
        int k2  = c4 * 2;
        int k2s = k2 ^ ((r & 7) << 2);
        *(uint2*)&As[r * 64 + k2s] = make_uint2(*(unsigned*)&h0, *(unsigned*)&h1);
    }
    // stage B: straight copy, already transposed+swizzled (4 uint4 per thread)
    #pragma unroll
    for (int it = 0; it < 4; ++it) {
        int i = tid + it * 256;
        ((uint4*)Bs)[i] = __ldg((const uint4*)g_Bsw + i);
    }
    __syncthreads();

    int w    = tid >> 5;
    int lane = tid & 31;
    int g = lane >> 2, c = lane & 3;
    int wm = w & 1, wn = w >> 1;       // 2 (M) x 4 (N)
    int sw = g << 2;

    float acc[2][2][4];
    #pragma unroll
    for (int mt = 0; mt < 2; ++mt)
        #pragma unroll
        for (int nt = 0; nt < 2; ++nt)
            #pragma unroll
            for (int x = 0; x < 4; ++x) acc[mt][nt][x] = 0.f;

    #pragma unroll
    for (int ks = 0; ks < 8; ++ks) {
        int k2a = (8 * ks + c)     ^ sw;
        int k2b = (8 * ks + c + 4) ^ sw;
        unsigned a[2][4];
        #pragma unroll
        for (int mt = 0; mt < 2; ++mt) {
            int r0 = wm * 32 + mt * 16 + g;
            a[mt][0] = As[r0 * 64 + k2a];
            a[mt][1] = As[(r0 + 8) * 64 + k2a];
            a[mt][2] = As[r0 * 64 + k2b];
            a[mt][3] = As[(r0 + 8) * 64 + k2b];
        }
        unsigned b[2][2];
        #pragma unroll
        for (int nt = 0; nt < 2; ++nt) {
            int n0 = wn * 16 + nt * 8 + g;
            b[nt][0] = Bs[n0 * 64 + k2a];
            b[nt][1] = Bs[n0 * 64 + k2b];
        }
        #pragma unroll
        for (int mt = 0; mt < 2; ++mt)
            #pragma unroll
            for (int nt = 0; nt < 2; ++nt)
                mma16816(acc[mt][nt], a[mt], b[nt]);
    }

    // write fp16 mirror: rows g / g+8, cols 2c,2c+1 within each 16x8 tile
    #pragma unroll
    for (int mt = 0; mt < 2; ++mt) {
        int r0 = base + wm * 32 + mt * 16 + g;
        #pragma unroll
        for (int nt = 0; nt < 2; ++nt) {
            int col2 = wn * 8 + nt * 4 + c;    // fp16x2 column index (0..31)
            if (r0 < N_NODES)
                g_x0h[(size_t)r0 * 32 + col2] =
                    __floats2half2_rn(acc[mt][nt][0], acc[mt][nt][1]);
            if (r0 + 8 < N_NODES)
                g_x0h[(size_t)(r0 + 8) * 32 + col2] =
                    __floats2half2_rn(acc[mt][nt][2], acc[mt][nt][3]);
        }
    }
}

// Push edge sweep, 4-edge pipelined (R8-proven).
__global__ void edge_kernel(const int* __restrict__ dst,
                            int which_x, int count_deg) {
    __shared__ __align__(16) float ws[R_REL * DIM];  // 16 KB
    for (int i = threadIdx.x; i < R_REL * DIM; i += blockDim.x) ws[i] = g_wrel[i];
    __syncthreads();

    const __half2* __restrict__ xh = which_x ? g_x1h : g_x0h;

    int G    = (gridDim.x * blockDim.x) >> 4;
    int g    = (blockIdx.x * blockDim.x + threadIdx.x) >> 4;
    int lane = threadIdx.x & 15;
    const int NQUADS = N_EDGES / 4;

    for (int q = g; q < NQUADS; q += G) {
        int e = q * 4;
        uint4 pk = __ldg((const uint4*)(g_pk + e));   // broadcast within group
        uint4 dd = *(const uint4*)(dst + e);          // broadcast within group

        uint2 p0 = __ldg((const uint2*)(xh + (size_t)(pk.x >> 6) * 32 + lane * 2));
        uint2 p1 = __ldg((const uint2*)(xh + (size_t)(pk.y >> 6) * 32 + lane * 2));
        uint2 p2 = __ldg((const uint2*)(xh + (size_t)(pk.z >> 6) * 32 + lane * 2));
        uint2 p3 = __ldg((const uint2*)(xh + (size_t)(pk.w >> 6) * 32 + lane * 2));

        unsigned pks[4] = {pk.x, pk.y, pk.z, pk.w};
        unsigned dds[4] = {dd.x, dd.y, dd.z, dd.w};
        uint2    pps[4] = {p0, p1, p2, p3};
        #pragma unroll
        for (int j = 0; j < 4; ++j) {
            float2 f0 = __half22float2(*(__half2*)&pps[j].x);
            float2 f1 = __half22float2(*(__half2*)&pps[j].y);
            float4 wv = *(const float4*)&ws[(pks[j] & 63u) * DIM + lane * 4];
            red_add_v4(g_agg + (size_t)dds[j] * DIM + lane * 4,
                       f0.x * wv.x, f0.y * wv.y, f1.x * wv.z, f1.y * wv.w);
            if (count_deg && lane == 0) red_add_s32(&g_deg[dds[j]], 1);
        }
    }
}

// finish (layer 1 only): x1 = tanh(agg/deg + b1) -> fp16 mirror; re-zero agg.
__global__ void finish_kernel(const float* __restrict__ b) {
    int i = blockIdx.x * blockDim.x + threadIdx.x;
    if (i >= N_NODES * (DIM / 4)) return;
    int n = i >> 4, c4 = (i & 15) * 4;
    float4 v = ((const float4*)g_agg)[i];
    int d = g_deg[n];
    float inv = 1.0f / (float)(d > 0 ? d : 1);
    float4 bb = *(const float4*)(b + c4);
    v.x = tanhf(v.x * inv + bb.x);
    v.y = tanhf(v.y * inv + bb.y);
    v.z = tanhf(v.z * inv + bb.z);
    v.w = tanhf(v.w * inv + bb.w);
    __half2 h0 = __floats2half2_rn(v.x, v.y);
    __half2 h1 = __floats2half2_rn(v.z, v.w);
    uint2 p = make_uint2(*(uint32_t*)&h0, *(uint32_t*)&h1);
    *(uint2*)(g_x1h + (size_t)n * 32 + (c4 >> 1)) = p;
    ((float4*)g_agg)[i] = make_float4(0.f, 0.f, 0.f, 0.f);
}

// Fused finish2 + out:  out = tanh(agg/deg + b2) @ fc2_w + fc2_b.
__global__ void out_kernel(const float* __restrict__ b2,
                           const float* __restrict__ fc2w,
                           const float* __restrict__ fc2b,
                           float* __restrict__ out) {
    __shared__ float ws[DIM * NCLS];  // 4 KB
    __shared__ float xs[16 * DIM];    // 4 KB
    int tid = threadIdx.x;
    for (int i = tid; i < DIM * NCLS; i += 256) ws[i] = fc2w[i];

    int base = blockIdx.x * 16;
    {
        int nl = tid >> 4, c4 = (tid & 15) * 4;
        int n = base + nl;
        float4 v = *(const float4*)&g_agg[(size_t)n * DIM + c4];
        int d = g_deg[n];
        float inv = 1.0f / (float)(d > 0 ? d : 1);
        float4 bb = *(const float4*)(b2 + c4);
        v.x = tanhf(v.x * inv + bb.x);
        v.y = tanhf(v.y * inv + bb.y);
        v.z = tanhf(v.z * inv + bb.z);
        v.w = tanhf(v.w * inv + bb.w);
        *(float4*)&xs[nl * DIM + c4] = v;
    }
    __syncthreads();

    int nl = tid >> 4, k = tid & 15;
    float acc = fc2b[k];
    #pragma unroll
    for (int c = 0; c < DIM; ++c)
        acc += xs[nl * DIM + c] * ws[c * NCLS + k];
    out[(size_t)(base + nl) * NCLS + k] = acc;
}

// ---------------- launch ----------------
extern "C" void kernel_launch(void* const* d_in, const int* in_sizes, int n_in,
                              void* d_out, int out_size) {
    const float* x_in   = (const float*)d_in[0];
    const float* rel_x  = (const float*)d_in[1];
    const int*   ei     = (const int*)  d_in[2];
    const int*   et     = (const int*)  d_in[3];
    const int*   rel_ei = (const int*)  d_in[4];
    const float* rel_ea = (const float*)d_in[5];
    const float* fc1    = (const float*)d_in[6];
    const float* W_nn   = (const float*)d_in[7];
    const float* b_nn   = (const float*)d_in[8];
    const float* b1     = (const float*)d_in[9];
    const float* b2     = (const float*)d_in[10];
    const float* fc2w   = (const float*)d_in[11];
    const float* fc2b   = (const float*)d_in[12];
    float* out = (float*)d_out;

    // proj_kernel is the 4th launch -> profiled this round.
    init_kernel<<<(N_EDGES + 255) / 256, 256>>>(ei, et);              // 1
    prep_b_kernel<<<16, 256>>>(fc1);                                  // 2
    rel_kernel<<<1, 1024>>>(rel_x, rel_ei, rel_ea, W_nn, b_nn);       // 3
    proj_kernel<<<(N_NODES + 63) / 64, 256>>>(x_in);                  // 4 <- profiled

    edge_kernel<<<2048, 256>>>(ei + N_EDGES, 0, /*count_deg=*/1);     // 5
    finish_kernel<<<(N_NODES * 16 + 255) / 256, 256>>>(b1);           // 6

    edge_kernel<<<2048, 256>>>(ei + N_EDGES, 1, /*count_deg=*/0);     // 7
    out_kernel<<<N_NODES / 16, 256>>>(b2, fc2w, fc2b, out);           // 8
}